// round 13
// baseline (speedup 1.0000x reference)
#include <cuda_runtime.h>
#include <cuda_fp16.h>
#include <math.h>
#include <stdint.h>

// Problem constants
#define BB 2
#define SS 2048
#define DD 2048
#define HH 16
#define KVH 2
#define HDIM 128
#define II 5504
#define MM (BB*SS)          // 4096
#define QKVN 2560           // 2048 q + 256 k + 256 v

// ---------------- scratch (device globals; allocation-free) ----------------
__device__ __half g_h   [MM*DD];
__device__ __half g_qkv [MM*QKVN];
__device__ __half g_attn[MM*DD];
__device__ float  g_h2  [MM*DD];
__device__ __half g_g   [MM*DD];
__device__ __half g_act [MM*II];          // silu(gate)*up
__device__ __half g_wqkv[QKVN*DD];
__device__ __half g_wo[DD*DD];
__device__ __half g_wgu[2*II*DD];         // interleaved gate/up weights
__device__ __half g_wd[DD*II];
__device__ float  g_bqkv[QKVN];

// ---------------- small helpers ----------------
__inline__ __device__ float warpReduceSum(float v) {
    #pragma unroll
    for (int m = 16; m; m >>= 1) v += __shfl_xor_sync(0xffffffffu, v, m);
    return v;
}
__device__ __forceinline__ uint32_t smem_u32(const void* p) {
    uint32_t a;
    asm("{ .reg .u64 t; cvta.to.shared.u64 t, %1; cvt.u32.u64 %0, t; }" : "=r"(a) : "l"(p));
    return a;
}
__device__ __forceinline__ void cp16(uint32_t s, const void* g) {
    asm volatile("cp.async.cg.shared.global [%0], [%1], 16;" :: "r"(s), "l"(g));
}
__device__ __forceinline__ void cp_commit() {
    asm volatile("cp.async.commit_group;" ::: "memory");
}
__device__ __forceinline__ void mma_f16(float* c, const uint32_t* a, const uint32_t* b) {
    asm volatile(
        "mma.sync.aligned.m16n8k16.row.col.f32.f16.f16.f32 "
        "{%0,%1,%2,%3}, {%4,%5,%6,%7}, {%8,%9}, {%0,%1,%2,%3};"
        : "+f"(c[0]), "+f"(c[1]), "+f"(c[2]), "+f"(c[3])
        : "r"(a[0]), "r"(a[1]), "r"(a[2]), "r"(a[3]), "r"(b[0]), "r"(b[1]));
}
__device__ __forceinline__ void ldm_x4(uint32_t* r, uint32_t addr) {
    asm volatile("ldmatrix.sync.aligned.m8n8.x4.shared.b16 {%0,%1,%2,%3}, [%4];"
        : "=r"(r[0]), "=r"(r[1]), "=r"(r[2]), "=r"(r[3]) : "r"(addr));
}
__device__ __forceinline__ float silu_f(float x) {
    return x / (1.f + __expf(-x));
}

// ---------------- FP16 mma.sync GEMM: C = A(MxK) @ B(NxK)^T ----------------
// CTA tile 256x128x64(halves), warp tile 64x64 (8 warps, 4 M x 2 N),
// 3-stage cp.async, ldmatrix.x4, pitch 72 halves (144B).
#define GPITCH_B  144
#define A_TILE_B  (256*GPITCH_B)
#define B_TILE_B  (128*GPITCH_B)
#define STAGE_B   (A_TILE_B + B_TILE_B)
#define GEMM_SMEM (3*STAGE_B)

// MODE 0: plain->half, MODE 1: +bias[col]->half, MODE 2: +aux[row*N+col]->float,
// MODE 3: silu-fused MLP (B interleaved gate/up) -> half
template<int MODE, typename CT>
__global__ __launch_bounds__(256) void hgemm_kernel(
    const __half* __restrict__ A, const __half* __restrict__ Bw,
    const float* __restrict__ aux, CT* __restrict__ C,
    int M, int N, int K)
{
    extern __shared__ __half smh[];
    const uint32_t sb = smem_u32(smh);
    const int tid  = threadIdx.x;
    const int lane = tid & 31;
    const int wid  = tid >> 5;
    const int wm   = wid & 3;
    const int wn   = wid >> 2;
    const int gi   = lane >> 2, tg = lane & 3;
    const int bn = blockIdx.x, bm = blockIdx.y;
    const __half* Ab = A  + (size_t)bm * 256 * K;
    const __half* Bb = Bw + (size_t)bn * 128 * K;

    const int nk = K >> 6;

    const int lrow = tid >> 3, lc = tid & 7;
    auto load_stage = [&](int stage, int kt) {
        const uint32_t as = sb + (uint32_t)stage * STAGE_B;
        const uint32_t bs = as + A_TILE_B;
        const __half* Asrc = Ab + (size_t)kt * 64;
        const __half* Bsrc = Bb + (size_t)kt * 64;
        #pragma unroll
        for (int u = 0; u < 8; u++) {
            int row = lrow + u * 32;
            cp16(as + (uint32_t)(row * GPITCH_B + lc * 16),
                 Asrc + (size_t)row * K + lc * 8);
        }
        #pragma unroll
        for (int u = 0; u < 4; u++) {
            int row = lrow + u * 32;
            cp16(bs + (uint32_t)(row * GPITCH_B + lc * 16),
                 Bsrc + (size_t)row * K + lc * 8);
        }
        cp_commit();
    };

    float acc[4][8][4];
    #pragma unroll
    for (int i = 0; i < 4; i++)
        #pragma unroll
        for (int j = 0; j < 8; j++)
            #pragma unroll
            for (int e = 0; e < 4; e++) acc[i][j][e] = 0.f;

    load_stage(0, 0);
    if (nk > 1) load_stage(1, 1);

    const uint32_t a_off = (uint32_t)((lane & 15) * GPITCH_B + ((lane >> 4) << 4));
    const uint32_t b_off = (uint32_t)(((lane & 7) + ((lane >> 4) << 3)) * GPITCH_B
                                      + (((lane >> 3) & 1) << 4));

    int rd = 0, wr = 2;
    for (int kt = 0; kt < nk; kt++) {
        if (kt + 1 < nk)
            asm volatile("cp.async.wait_group 1;" ::: "memory");
        else
            asm volatile("cp.async.wait_group 0;" ::: "memory");
        __syncthreads();
        if (kt + 2 < nk) load_stage(wr, kt + 2);

        const uint32_t as = sb + (uint32_t)rd * STAGE_B;
        const uint32_t bs = as + A_TILE_B;
        const uint32_t a_base = as + (uint32_t)(wm * 64) * GPITCH_B + a_off;
        const uint32_t b_base = bs + (uint32_t)(wn * 64) * GPITCH_B + b_off;

        #pragma unroll
        for (int kk = 0; kk < 4; kk++) {
            const uint32_t k0b = kk * 32;
            uint32_t a[4][4], b[8][2];
            #pragma unroll
            for (int mt = 0; mt < 4; mt++)
                ldm_x4(a[mt], a_base + (uint32_t)(mt * 16) * GPITCH_B + k0b);
            #pragma unroll
            for (int nb = 0; nb < 4; nb++) {
                uint32_t r[4];
                ldm_x4(r, b_base + (uint32_t)(nb * 16) * GPITCH_B + k0b);
                b[2*nb][0] = r[0]; b[2*nb][1] = r[1];
                b[2*nb+1][0] = r[2]; b[2*nb+1][1] = r[3];
            }
            #pragma unroll
            for (int mt = 0; mt < 4; mt++)
                #pragma unroll
                for (int nt = 0; nt < 8; nt++)
                    mma_f16(acc[mt][nt], a[mt], b[nt]);
        }
        rd = (rd == 2) ? 0 : rd + 1;
        wr = (wr == 2) ? 0 : wr + 1;
    }

    if (MODE == 3) {
        const int j = bn * 2 + wn;
        #pragma unroll
        for (int mt = 0; mt < 4; mt++) {
            const int r0 = bm * 256 + wm * 64 + mt * 16 + gi;
            #pragma unroll
            for (int jt = 0; jt < 4; jt++) {
                const int c = j * 32 + jt * 8 + 2*tg;
                float a00 = silu_f(acc[mt][jt][0]) * acc[mt][jt+4][0];
                float a01 = silu_f(acc[mt][jt][1]) * acc[mt][jt+4][1];
                float a10 = silu_f(acc[mt][jt][2]) * acc[mt][jt+4][2];
                float a11 = silu_f(acc[mt][jt][3]) * acc[mt][jt+4][3];
                *(__half2*)((__half*)C + (size_t)r0 * N + c) = __floats2half2_rn(a00, a01);
                *(__half2*)((__half*)C + (size_t)(r0 + 8) * N + c) = __floats2half2_rn(a10, a11);
            }
        }
        return;
    }
    #pragma unroll
    for (int mt = 0; mt < 4; mt++) {
        const int r0 = bm * 256 + wm * 64 + mt * 16 + gi;
        #pragma unroll
        for (int nt = 0; nt < 8; nt++) {
            const int c = bn * 128 + wn * 64 + nt * 8 + 2*tg;
            float v00 = acc[mt][nt][0], v01 = acc[mt][nt][1];
            float v10 = acc[mt][nt][2], v11 = acc[mt][nt][3];
            if (MODE == 1) {
                float bx = aux[c], by = aux[c + 1];
                v00 += bx; v01 += by; v10 += bx; v11 += by;
            }
            if (MODE == 2) {
                const float2 a0 = *(const float2*)(aux + (size_t)r0 * N + c);
                const float2 a1 = *(const float2*)(aux + (size_t)(r0 + 8) * N + c);
                v00 += a0.x; v01 += a0.y; v10 += a1.x; v11 += a1.y;
                *(float2*)((float*)C + (size_t)r0 * N + c) = make_float2(v00, v01);
                *(float2*)((float*)C + (size_t)(r0 + 8) * N + c) = make_float2(v10, v11);
            } else {
                *(__half2*)((__half*)C + (size_t)r0 * N + c) = __floats2half2_rn(v00, v01);
                *(__half2*)((__half*)C + (size_t)(r0 + 8) * N + c) = __floats2half2_rn(v10, v11);
            }
        }
    }
}

// ---------------- RMSNorm: fp32 in -> half out ----------------
__global__ __launch_bounds__(256) void rmsnorm_kernel(
    const float* __restrict__ x, const float* __restrict__ w, __half* __restrict__ out)
{
    int row = blockIdx.x;
    const float4* xr = (const float4*)(x + (size_t)row * DD);
    const float4* wr = (const float4*)w;
    float4 v0 = xr[threadIdx.x];
    float4 v1 = xr[threadIdx.x + 256];
    float s = v0.x*v0.x + v0.y*v0.y + v0.z*v0.z + v0.w*v0.w
            + v1.x*v1.x + v1.y*v1.y + v1.z*v1.z + v1.w*v1.w;
    s = warpReduceSum(s);
    __shared__ float smw[8];
    __shared__ float sinv;
    if ((threadIdx.x & 31) == 0) smw[threadIdx.x >> 5] = s;
    __syncthreads();
    if (threadIdx.x == 0) {
        float t = 0.f;
        #pragma unroll
        for (int i = 0; i < 8; i++) t += smw[i];
        sinv = rsqrtf(t * (1.0f / DD) + 1e-6f);
    }
    __syncthreads();
    float inv = sinv;
    float4 w0 = wr[threadIdx.x], w1 = wr[threadIdx.x + 256];
    __half2* orow = (__half2*)(out + (size_t)row * DD);
    orow[2*threadIdx.x]       = __floats2half2_rn(v0.x*inv*w0.x, v0.y*inv*w0.y);
    orow[2*threadIdx.x + 1]   = __floats2half2_rn(v0.z*inv*w0.z, v0.w*inv*w0.w);
    orow[512 + 2*threadIdx.x] = __floats2half2_rn(v1.x*inv*w1.x, v1.y*inv*w1.y);
    orow[513 + 2*threadIdx.x] = __floats2half2_rn(v1.z*inv*w1.z, v1.w*inv*w1.w);
}

// ---------------- fp32 -> fp16 conversion ----------------
__global__ __launch_bounds__(256) void f2h_kernel(
    const float* __restrict__ in, __half* __restrict__ out)
{
    size_t i = (size_t)blockIdx.x * 256 + threadIdx.x;
    float4 v = ((const float4*)in)[i];
    ((__half2*)out)[2*i]   = __floats2half2_rn(v.x, v.y);
    ((__half2*)out)[2*i+1] = __floats2half2_rn(v.z, v.w);
}

// ---------------- gate/up weights -> interleaved fp16 ----------------
__global__ __launch_bounds__(256) void f2h_ilv_kernel(
    const float* __restrict__ wg, const float* __restrict__ wu, __half* __restrict__ out)
{
    size_t i = (size_t)blockIdx.x * 256 + threadIdx.x;
    int c4 = (int)(i % (DD/4));
    int r  = (int)(i / (DD/4));
    int rg = 64*(r >> 5) + (r & 31);
    float4 gv = ((const float4*)wg)[i];
    float4 uv = ((const float4*)wu)[i];
    __half2* og = (__half2*)(out + (size_t)rg * DD + c4*4);
    og[0] = __floats2half2_rn(gv.x, gv.y);
    og[1] = __floats2half2_rn(gv.z, gv.w);
    __half2* ou = (__half2*)(out + (size_t)(rg + 32) * DD + c4*4);
    ou[0] = __floats2half2_rn(uv.x, uv.y);
    ou[1] = __floats2half2_rn(uv.z, uv.w);
}

// ---------------- bias concat (q|k|v) ----------------
__global__ void bias_concat_kernel(
    const float* __restrict__ bq, const float* __restrict__ bk,
    const float* __restrict__ bv, float* __restrict__ o)
{
    int i = blockIdx.x * 256 + threadIdx.x;
    if (i < 2048) o[i] = bq[i];
    else if (i < 2304) o[i] = bk[i - 2048];
    else if (i < QKVN) o[i] = bv[i - 2304];
}

// ---------------- RoPE (in place, half): buf row pitch QKVN ----------------
__global__ __launch_bounds__(256) void rope_kernel(
    __half* __restrict__ buf, int nh, int off)
{
    int idx = blockIdx.x * 256 + threadIdx.x;
    int d   = idx & 63;
    int t   = idx >> 6;
    int hh  = t % nh;
    int m   = t / nh;
    int pos = m & (SS - 1);
    float inv = exp2f(-(float)d * (13.287712379549449f / 64.0f));   // 10000^(-d/64)
    float fr  = (float)pos * inv;
    float c, sn;
    __sincosf(fr, &sn, &c);
    __half* p = buf + (size_t)m * QKVN + off + hh * HDIM + d;
    float x1 = __half2float(p[0]), x2 = __half2float(p[64]);
    p[0]  = __float2half_rn(x1 * c - x2 * sn);
    p[64] = __float2half_rn(x2 * c + x1 * sn);
}

// ---------------- Flash attention (causal, GQA), fp16 mma, cp.async KV ----------------
#define FQP 136
#define FPP 72
#define FA_SMEM ((128*FQP + 4*64*FQP + 128*FPP) * 2)   // Q + 2-stage K/V + P

__global__ __launch_bounds__(256, 1) void flash_mma_kernel(
    const __half* __restrict__ QKV, __half* __restrict__ O)
{
    extern __shared__ __half smh[];
    __half* Qs  = smh;                       // [128][136]
    __half* Kst = Qs + 128*FQP;              // [2][64][136]
    __half* Vst = Kst + 2*64*FQP;            // [2][64][136]
    __half* Ps  = Vst + 2*64*FQP;            // [128][72]
    const uint32_t sbK = smem_u32(Kst);
    const uint32_t sbV = smem_u32(Vst);

    const int qt = blockIdx.x, bh = blockIdx.y;
    const int b = bh >> 4, h = bh & 15, kvh = h >> 3;
    const int tid = threadIdx.x, lane = tid & 31, wid = tid >> 5;
    const int gi = lane >> 2, tg = lane & 3;
    const float scale = 0.088388347648318447f;

    for (int f = tid; f < 2048; f += 256) {
        int r = f >> 4, c8 = f & 15;
        *(uint4*)(Qs + r*FQP + c8*8) =
            *(const uint4*)(QKV + (size_t)(b*SS + qt*128 + r) * QKVN + h*HDIM + c8*8);
    }

    auto load_kv = [&](int st, int kt) {
        const uint32_t kb = sbK + (uint32_t)st * (64*FQP*2);
        const uint32_t vb = sbV + (uint32_t)st * (64*FQP*2);
        #pragma unroll
        for (int u = 0; u < 4; u++) {
            int f = tid + u * 256;
            int r = f >> 4, c8 = f & 15;
            size_t base = (size_t)(b*SS + kt*64 + r) * QKVN + kvh * HDIM;
            cp16(kb + (uint32_t)(r * (FQP*2) + c8 * 16), QKV + base + 2048 + c8*8);
            cp16(vb + (uint32_t)(r * (FQP*2) + c8 * 16), QKV + base + 2304 + c8*8);
        }
        cp_commit();
    };

    float oacc[16][4];
    #pragma unroll
    for (int i = 0; i < 16; i++)
        #pragma unroll
        for (int e = 0; e < 4; e++) oacc[i][e] = 0.f;
    float mrow[2] = {-1e30f, -1e30f}, lrow[2] = {0.f, 0.f};

    const int r0 = wid*16 + gi;
    const int kmax = 2*qt + 2;

    load_kv(0, 0);

    for (int kt = 0; kt < kmax; kt++) {
        __syncthreads();
        if (kt + 1 < kmax) {
            load_kv((kt + 1) & 1, kt + 1);
            asm volatile("cp.async.wait_group 1;" ::: "memory");
        } else {
            asm volatile("cp.async.wait_group 0;" ::: "memory");
        }
        __syncthreads();

        if (kt*64 > qt*128 + wid*16 + 15) continue;

        const __half* Ks = Kst + (kt & 1) * 64*FQP;
        const __half* Vs = Vst + (kt & 1) * 64*FQP;

        float sa[8][4];
        #pragma unroll
        for (int nt = 0; nt < 8; nt++)
            #pragma unroll
            for (int e = 0; e < 4; e++) sa[nt][e] = 0.f;
        #pragma unroll
        for (int ks = 0; ks < 8; ks++) {
            const int k0 = ks*16 + 2*tg;
            uint32_t a[4];
            a[0] = *(const uint32_t*)(Qs + r0*FQP + k0);
            a[1] = *(const uint32_t*)(Qs + (r0+8)*FQP + k0);
            a[2] = *(const uint32_t*)(Qs + r0*FQP + k0 + 8);
            a[3] = *(const uint32_t*)(Qs + (r0+8)*FQP + k0 + 8);
            #pragma unroll
            for (int nt = 0; nt < 8; nt++) {
                const int n = nt*8 + gi;
                uint32_t bb[2];
                bb[0] = *(const uint32_t*)(Ks + n*FQP + k0);
                bb[1] = *(const uint32_t*)(Ks + n*FQP + k0 + 8);
                mma_f16(sa[nt], a, bb);
            }
        }
        #pragma unroll
        for (int nt = 0; nt < 8; nt++)
            #pragma unroll
            for (int e = 0; e < 4; e++) sa[nt][e] *= scale;
        if (kt >= 2*qt) {
            const int qr0 = qt*128 + r0, qr1 = qr0 + 8;
            #pragma unroll
            for (int nt = 0; nt < 8; nt++) {
                int kc = kt*64 + nt*8 + 2*tg;
                if (kc     > qr0) sa[nt][0] = -1e30f;
                if (kc + 1 > qr0) sa[nt][1] = -1e30f;
                if (kc     > qr1) sa[nt][2] = -1e30f;
                if (kc + 1 > qr1) sa[nt][3] = -1e30f;
            }
        }

        float mx0 = -1e30f, mx1 = -1e30f;
        #pragma unroll
        for (int nt = 0; nt < 8; nt++) {
            mx0 = fmaxf(mx0, fmaxf(sa[nt][0], sa[nt][1]));
            mx1 = fmaxf(mx1, fmaxf(sa[nt][2], sa[nt][3]));
        }
        mx0 = fmaxf(mx0, __shfl_xor_sync(0xffffffffu, mx0, 1));
        mx0 = fmaxf(mx0, __shfl_xor_sync(0xffffffffu, mx0, 2));
        mx1 = fmaxf(mx1, __shfl_xor_sync(0xffffffffu, mx1, 1));
        mx1 = fmaxf(mx1, __shfl_xor_sync(0xffffffffu, mx1, 2));
        const float mn0 = fmaxf(mrow[0], mx0), mn1 = fmaxf(mrow[1], mx1);
        const float cr0 = __expf(mrow[0] - mn0), cr1 = __expf(mrow[1] - mn1);
        float s0 = 0.f, s1 = 0.f;
        #pragma unroll
        for (int nt = 0; nt < 8; nt++) {
            __half2 p0 = __floats2half2_rn(__expf(sa[nt][0] - mn0), __expf(sa[nt][1] - mn0));
            __half2 p1 = __floats2half2_rn(__expf(sa[nt][2] - mn1), __expf(sa[nt][3] - mn1));
            float2 p0f = __half22float2(p0), p1f = __half22float2(p1);
            s0 += p0f.x + p0f.y;
            s1 += p1f.x + p1f.y;
            *(__half2*)(Ps + r0*FPP + nt*8 + 2*tg)     = p0;
            *(__half2*)(Ps + (r0+8)*FPP + nt*8 + 2*tg) = p1;
        }
        s0 += __shfl_xor_sync(0xffffffffu, s0, 1);
        s0 += __shfl_xor_sync(0xffffffffu, s0, 2);
        s1 += __shfl_xor_sync(0xffffffffu, s1, 1);
        s1 += __shfl_xor_sync(0xffffffffu, s1, 2);
        lrow[0] = lrow[0]*cr0 + s0;
        lrow[1] = lrow[1]*cr1 + s1;
        mrow[0] = mn0; mrow[1] = mn1;
        #pragma unroll
        for (int nt = 0; nt < 16; nt++) {
            oacc[nt][0] *= cr0; oacc[nt][1] *= cr0;
            oacc[nt][2] *= cr1; oacc[nt][3] *= cr1;
        }
        __syncwarp();

        #pragma unroll
        for (int ks = 0; ks < 4; ks++) {
            const int k0 = ks*16 + 2*tg;
            uint32_t a[4];
            a[0] = *(const uint32_t*)(Ps + r0*FPP + k0);
            a[1] = *(const uint32_t*)(Ps + (r0+8)*FPP + k0);
            a[2] = *(const uint32_t*)(Ps + r0*FPP + k0 + 8);
            a[3] = *(const uint32_t*)(Ps + (r0+8)*FPP + k0 + 8);
            #pragma unroll
            for (int ntp = 0; ntp < 8; ntp++) {
                int kvrow = ks*16 + (lane & 15);
                int dcol  = (ntp*2 + (lane >> 4)) * 8;
                uint32_t addr = smem_u32(Vs + kvrow*FQP + dcol);
                uint32_t b0, b1, b2, b3;
                asm volatile(
                    "ldmatrix.sync.aligned.m8n8.x4.trans.shared.b16 {%0,%1,%2,%3}, [%4];"
                    : "=r"(b0), "=r"(b1), "=r"(b2), "=r"(b3) : "r"(addr));
                uint32_t bb0[2] = {b0, b1}, bb1[2] = {b2, b3};
                mma_f16(oacc[2*ntp],     a, bb0);
                mma_f16(oacc[2*ntp + 1], a, bb1);
            }
        }
    }

    const float inv0 = 1.0f / lrow[0], inv1 = 1.0f / lrow[1];
    __half* op0 = O + (size_t)(b*SS + qt*128 + r0)     * DD + h*HDIM + 2*tg;
    __half* op1 = O + (size_t)(b*SS + qt*128 + r0 + 8) * DD + h*HDIM + 2*tg;
    #pragma unroll
    for (int nt = 0; nt < 16; nt++) {
        *(__half2*)(op0 + nt*8) = __floats2half2_rn(oacc[nt][0]*inv0, oacc[nt][1]*inv0);
        *(__half2*)(op1 + nt*8) = __floats2half2_rn(oacc[nt][2]*inv1, oacc[nt][3]*inv1);
    }
}

// ---------------- launch ----------------
extern "C" void kernel_launch(void* const* d_in, const int* in_sizes, int n_in,
                              void* d_out, int out_size)
{
    (void)in_sizes; (void)n_in; (void)out_size;
    const float* x   = (const float*)d_in[0];
    const float* ln1 = (const float*)d_in[2];
    const float* wq  = (const float*)d_in[3];
    const float* bq  = (const float*)d_in[4];
    const float* wk  = (const float*)d_in[5];
    const float* bk  = (const float*)d_in[6];
    const float* wv  = (const float*)d_in[7];
    const float* bv  = (const float*)d_in[8];
    const float* wo  = (const float*)d_in[9];
    const float* ln2 = (const float*)d_in[10];
    const float* wg  = (const float*)d_in[11];
    const float* wu  = (const float*)d_in[12];
    const float* wd  = (const float*)d_in[13];
    float* out = (float*)d_out;

    __half *h, *qkv, *attn, *g, *act;
    __half *rwqkv, *rwo, *rwgu, *rwd;
    float *h2, *bqkv;
    cudaGetSymbolAddress((void**)&h,     g_h);
    cudaGetSymbolAddress((void**)&qkv,   g_qkv);
    cudaGetSymbolAddress((void**)&attn,  g_attn);
    cudaGetSymbolAddress((void**)&h2,    g_h2);
    cudaGetSymbolAddress((void**)&g,     g_g);
    cudaGetSymbolAddress((void**)&act,   g_act);
    cudaGetSymbolAddress((void**)&rwqkv, g_wqkv);
    cudaGetSymbolAddress((void**)&rwo,   g_wo);
    cudaGetSymbolAddress((void**)&rwgu,  g_wgu);
    cudaGetSymbolAddress((void**)&rwd,   g_wd);
    cudaGetSymbolAddress((void**)&bqkv,  g_bqkv);

    cudaFuncSetAttribute((const void*)hgemm_kernel<1,__half>, cudaFuncAttributeMaxDynamicSharedMemorySize, GEMM_SMEM);
    cudaFuncSetAttribute((const void*)hgemm_kernel<2,float>,  cudaFuncAttributeMaxDynamicSharedMemorySize, GEMM_SMEM);
    cudaFuncSetAttribute((const void*)hgemm_kernel<3,__half>, cudaFuncAttributeMaxDynamicSharedMemorySize, GEMM_SMEM);
    cudaFuncSetAttribute((const void*)flash_mma_kernel, cudaFuncAttributeMaxDynamicSharedMemorySize, FA_SMEM);

    // Side stream + events (created once; same launch sequence every call)
    static cudaStream_t s2 = nullptr;
    static cudaEvent_t eFork = nullptr, eWo = nullptr, eGu = nullptr, eWd = nullptr;
    if (s2 == nullptr) {
        cudaStreamCreateWithFlags(&s2, cudaStreamNonBlocking);
        cudaEventCreateWithFlags(&eFork, cudaEventDisableTiming);
        cudaEventCreateWithFlags(&eWo,   cudaEventDisableTiming);
        cudaEventCreateWithFlags(&eGu,   cudaEventDisableTiming);
        cudaEventCreateWithFlags(&eWd,   cudaEventDisableTiming);
    }

    // ---- fork: late-needed weight conversions run on s2, overlapping QKV+attention ----
    cudaEventRecord(eFork, 0);
    cudaStreamWaitEvent(s2, eFork, 0);
    f2h_kernel<<<(DD*DD/4)/256, 256, 0, s2>>>(wo, rwo);
    cudaEventRecord(eWo, s2);
    f2h_ilv_kernel<<<(II*DD/4)/256, 256, 0, s2>>>(wg, wu, rwgu);
    cudaEventRecord(eGu, s2);
    f2h_kernel<<<(DD*II/4)/256, 256, 0, s2>>>(wd, rwd);
    cudaEventRecord(eWd, s2);

    // ---- main stream: only QKV weights needed up front ----
    f2h_kernel<<<(DD*DD/4)/256, 256>>>(wq, rwqkv);
    f2h_kernel<<<(256*DD/4)/256, 256>>>(wk, rwqkv + 2048*DD);
    f2h_kernel<<<(256*DD/4)/256, 256>>>(wv, rwqkv + 2304*DD);
    bias_concat_kernel<<<10, 256>>>(bq, bk, bv, bqkv);

    // 1. h = rmsnorm(x, ln1) -> half
    rmsnorm_kernel<<<MM, 256>>>(x, ln1, h);

    // 2. fused qkv projection (+bias)
    hgemm_kernel<1,__half><<<dim3(QKVN/128, MM/256), 256, GEMM_SMEM>>>(h, rwqkv, bqkv, qkv, MM, QKVN, DD);

    // 3. RoPE (q at offset 0, k at 2048)
    rope_kernel<<<(MM*HH*64)/256, 256>>>(qkv, HH, 0);
    rope_kernel<<<(MM*KVH*64)/256, 256>>>(qkv, KVH, 2048);

    // 4. attention
    flash_mma_kernel<<<dim3(SS/128, BB*HH), 256, FA_SMEM>>>(qkv, attn);

    // 5. h2 = x + attn @ wo^T (fp32) — needs rwo
    cudaStreamWaitEvent(0, eWo, 0);
    hgemm_kernel<2,float><<<dim3(DD/128, MM/256), 256, GEMM_SMEM>>>(attn, rwo, x, h2, MM, DD, DD);

    // 6. g = rmsnorm(h2, ln2) -> half
    rmsnorm_kernel<<<MM, 256>>>(h2, ln2, g);

    // 7. fused MLP gate/up + silu — needs rwgu
    cudaStreamWaitEvent(0, eGu, 0);
    hgemm_kernel<3,__half><<<dim3(2*II/128, MM/256), 256, GEMM_SMEM>>>(g, rwgu, nullptr, act, MM, II, DD);

    // 8. out = h2 + act @ wd^T (fp32) — needs rwd
    cudaStreamWaitEvent(0, eWd, 0);
    hgemm_kernel<2,float><<<dim3(DD/128, MM/256), 256, GEMM_SMEM>>>(act, rwd, h2, out, MM, DD, II);
}

// round 14
// speedup vs baseline: 1.1512x; 1.1512x over previous
#include <cuda_runtime.h>
#include <cuda_fp16.h>
#include <math.h>
#include <stdint.h>

// Problem constants
#define BB 2
#define SS 2048
#define DD 2048
#define HH 16
#define KVH 2
#define HDIM 128
#define II 5504
#define MM (BB*SS)          // 4096
#define QKVN 2560           // 2048 q + 256 k + 256 v

// ---------------- scratch (device globals; allocation-free) ----------------
__device__ __half g_h   [MM*DD];
__device__ __half g_qkv [MM*QKVN];
__device__ __half g_attn[MM*DD];
__device__ float  g_h2  [MM*DD];
__device__ __half g_g   [MM*DD];
__device__ __half g_act [MM*II];          // silu(gate)*up
__device__ __half g_wqkv[QKVN*DD];
__device__ __half g_wo[DD*DD];
__device__ __half g_wgu[2*II*DD];         // interleaved gate/up weights (16-row granules)
__device__ __half g_wd[DD*II];
__device__ float  g_bqkv[QKVN];
__device__ float2 g_rope[SS*64];          // (cos, sin) per (pos, d)

// ---------------- small helpers ----------------
__inline__ __device__ float warpReduceSum(float v) {
    #pragma unroll
    for (int m = 16; m; m >>= 1) v += __shfl_xor_sync(0xffffffffu, v, m);
    return v;
}
__device__ __forceinline__ uint32_t smem_u32(const void* p) {
    uint32_t a;
    asm("{ .reg .u64 t; cvta.to.shared.u64 t, %1; cvt.u32.u64 %0, t; }" : "=r"(a) : "l"(p));
    return a;
}
__device__ __forceinline__ void cp16(uint32_t s, const void* g) {
    asm volatile("cp.async.cg.shared.global [%0], [%1], 16;" :: "r"(s), "l"(g));
}
__device__ __forceinline__ void cp_commit() {
    asm volatile("cp.async.commit_group;" ::: "memory");
}
__device__ __forceinline__ void mma_f16(float* c, const uint32_t* a, const uint32_t* b) {
    asm volatile(
        "mma.sync.aligned.m16n8k16.row.col.f32.f16.f16.f32 "
        "{%0,%1,%2,%3}, {%4,%5,%6,%7}, {%8,%9}, {%0,%1,%2,%3};"
        : "+f"(c[0]), "+f"(c[1]), "+f"(c[2]), "+f"(c[3])
        : "r"(a[0]), "r"(a[1]), "r"(a[2]), "r"(a[3]), "r"(b[0]), "r"(b[1]));
}
__device__ __forceinline__ void ldm_x4(uint32_t* r, uint32_t addr) {
    asm volatile("ldmatrix.sync.aligned.m8n8.x4.shared.b16 {%0,%1,%2,%3}, [%4];"
        : "=r"(r[0]), "=r"(r[1]), "=r"(r[2]), "=r"(r[3]) : "r"(addr));
}
__device__ __forceinline__ float silu_f(float x) {
    return x / (1.f + __expf(-x));
}

// ---------------- FP16 mma.sync GEMM: C = A(MxK) @ B(NxK)^T ----------------
// CTA tile 128x128x64, warp tile 64x32 (8 warps, 2 M x 4 N), 3-stage cp.async,
// ldmatrix.x4, pitch 72 halves. 110.6KB smem -> 2 CTAs/SM (finer quantization).
#define GPITCH_B  144
#define A_TILE_B  (128*GPITCH_B)
#define B_TILE_B  (128*GPITCH_B)
#define STAGE_B   (A_TILE_B + B_TILE_B)
#define GEMM_SMEM (3*STAGE_B)              // 110592

// MODE 0: plain->half, MODE 1: +bias[col]->half, MODE 2: +aux[row*N+col]->float,
// MODE 3: silu-fused MLP (B interleaved gate/up, 16-row granules) -> half
template<int MODE, typename CT>
__global__ __launch_bounds__(256, 2) void hgemm_kernel(
    const __half* __restrict__ A, const __half* __restrict__ Bw,
    const float* __restrict__ aux, CT* __restrict__ C,
    int M, int N, int K)
{
    extern __shared__ __half smh[];
    const uint32_t sb = smem_u32(smh);
    const int tid  = threadIdx.x;
    const int lane = tid & 31;
    const int wid  = tid >> 5;
    const int wm   = wid >> 2;           // 0..1 (M, 64 rows)
    const int wn   = wid & 3;            // 0..3 (N, 32 cols)
    const int gi   = lane >> 2, tg = lane & 3;
    const int bn = blockIdx.x, bm = blockIdx.y;
    const __half* Ab = A  + (size_t)bm * 128 * K;
    const __half* Bb = Bw + (size_t)bn * 128 * K;

    const int nk = K >> 6;

    const int lrow = tid >> 3, lc = tid & 7;
    auto load_stage = [&](int stage, int kt) {
        const uint32_t as = sb + (uint32_t)stage * STAGE_B;
        const uint32_t bs = as + A_TILE_B;
        const __half* Asrc = Ab + (size_t)kt * 64;
        const __half* Bsrc = Bb + (size_t)kt * 64;
        #pragma unroll
        for (int u = 0; u < 4; u++) {
            int row = lrow + u * 32;
            cp16(as + (uint32_t)(row * GPITCH_B + lc * 16),
                 Asrc + (size_t)row * K + lc * 8);
        }
        #pragma unroll
        for (int u = 0; u < 4; u++) {
            int row = lrow + u * 32;
            cp16(bs + (uint32_t)(row * GPITCH_B + lc * 16),
                 Bsrc + (size_t)row * K + lc * 8);
        }
        cp_commit();
    };

    float acc[4][4][4];
    #pragma unroll
    for (int i = 0; i < 4; i++)
        #pragma unroll
        for (int j = 0; j < 4; j++)
            #pragma unroll
            for (int e = 0; e < 4; e++) acc[i][j][e] = 0.f;

    load_stage(0, 0);
    if (nk > 1) load_stage(1, 1);

    const uint32_t a_off = (uint32_t)((lane & 15) * GPITCH_B + ((lane >> 4) << 4));
    const uint32_t b_off = (uint32_t)(((lane & 7) + ((lane >> 4) << 3)) * GPITCH_B
                                      + (((lane >> 3) & 1) << 4));

    int rd = 0, wr = 2;
    for (int kt = 0; kt < nk; kt++) {
        if (kt + 1 < nk)
            asm volatile("cp.async.wait_group 1;" ::: "memory");
        else
            asm volatile("cp.async.wait_group 0;" ::: "memory");
        __syncthreads();
        if (kt + 2 < nk) load_stage(wr, kt + 2);

        const uint32_t as = sb + (uint32_t)rd * STAGE_B;
        const uint32_t bs = as + A_TILE_B;
        const uint32_t a_base = as + (uint32_t)(wm * 64) * GPITCH_B + a_off;
        const uint32_t b_base = bs + (uint32_t)(wn * 32) * GPITCH_B + b_off;

        #pragma unroll
        for (int kk = 0; kk < 4; kk++) {
            const uint32_t k0b = kk * 32;
            uint32_t a[4][4], b[4][2];
            #pragma unroll
            for (int mt = 0; mt < 4; mt++)
                ldm_x4(a[mt], a_base + (uint32_t)(mt * 16) * GPITCH_B + k0b);
            #pragma unroll
            for (int nb = 0; nb < 2; nb++) {
                uint32_t r[4];
                ldm_x4(r, b_base + (uint32_t)(nb * 16) * GPITCH_B + k0b);
                b[2*nb][0] = r[0]; b[2*nb][1] = r[1];
                b[2*nb+1][0] = r[2]; b[2*nb+1][1] = r[3];
            }
            #pragma unroll
            for (int mt = 0; mt < 4; mt++)
                #pragma unroll
                for (int nt = 0; nt < 4; nt++)
                    mma_f16(acc[mt][nt], a[mt], b[nt]);
        }
        rd = (rd == 2) ? 0 : rd + 1;
        wr = (wr == 2) ? 0 : wr + 1;
    }

    if (MODE == 3) {
        // B rows [32j..32j+15] = gate[16j..], [32j+16..32j+31] = up[16j..]
        // warp wn covers B rows bn*128 + wn*32 -> block j = bn*4 + wn
        const int j = bn * 4 + wn;
        #pragma unroll
        for (int mt = 0; mt < 4; mt++) {
            const int r0 = bm * 128 + wm * 64 + mt * 16 + gi;
            #pragma unroll
            for (int jt = 0; jt < 2; jt++) {
                const int c = j * 16 + jt * 8 + 2*tg;
                float a00 = silu_f(acc[mt][jt][0]) * acc[mt][jt+2][0];
                float a01 = silu_f(acc[mt][jt][1]) * acc[mt][jt+2][1];
                float a10 = silu_f(acc[mt][jt][2]) * acc[mt][jt+2][2];
                float a11 = silu_f(acc[mt][jt][3]) * acc[mt][jt+2][3];
                *(__half2*)((__half*)C + (size_t)r0 * N + c) = __floats2half2_rn(a00, a01);
                *(__half2*)((__half*)C + (size_t)(r0 + 8) * N + c) = __floats2half2_rn(a10, a11);
            }
        }
        return;
    }
    #pragma unroll
    for (int mt = 0; mt < 4; mt++) {
        const int r0 = bm * 128 + wm * 64 + mt * 16 + gi;
        #pragma unroll
        for (int nt = 0; nt < 4; nt++) {
            const int c = bn * 128 + wn * 32 + nt * 8 + 2*tg;
            float v00 = acc[mt][nt][0], v01 = acc[mt][nt][1];
            float v10 = acc[mt][nt][2], v11 = acc[mt][nt][3];
            if (MODE == 1) {
                float bx = aux[c], by = aux[c + 1];
                v00 += bx; v01 += by; v10 += bx; v11 += by;
            }
            if (MODE == 2) {
                const float2 a0 = *(const float2*)(aux + (size_t)r0 * N + c);
                const float2 a1 = *(const float2*)(aux + (size_t)(r0 + 8) * N + c);
                v00 += a0.x; v01 += a0.y; v10 += a1.x; v11 += a1.y;
                *(float2*)((float*)C + (size_t)r0 * N + c) = make_float2(v00, v01);
                *(float2*)((float*)C + (size_t)(r0 + 8) * N + c) = make_float2(v10, v11);
            } else {
                *(__half2*)((__half*)C + (size_t)r0 * N + c) = __floats2half2_rn(v00, v01);
                *(__half2*)((__half*)C + (size_t)(r0 + 8) * N + c) = __floats2half2_rn(v10, v11);
            }
        }
    }
}

// ---------------- RMSNorm: fp32 in -> half out ----------------
__global__ __launch_bounds__(256) void rmsnorm_kernel(
    const float* __restrict__ x, const float* __restrict__ w, __half* __restrict__ out)
{
    int row = blockIdx.x;
    const float4* xr = (const float4*)(x + (size_t)row * DD);
    const float4* wr = (const float4*)w;
    float4 v0 = xr[threadIdx.x];
    float4 v1 = xr[threadIdx.x + 256];
    float s = v0.x*v0.x + v0.y*v0.y + v0.z*v0.z + v0.w*v0.w
            + v1.x*v1.x + v1.y*v1.y + v1.z*v1.z + v1.w*v1.w;
    s = warpReduceSum(s);
    __shared__ float smw[8];
    __shared__ float sinv;
    if ((threadIdx.x & 31) == 0) smw[threadIdx.x >> 5] = s;
    __syncthreads();
    if (threadIdx.x == 0) {
        float t = 0.f;
        #pragma unroll
        for (int i = 0; i < 8; i++) t += smw[i];
        sinv = rsqrtf(t * (1.0f / DD) + 1e-6f);
    }
    __syncthreads();
    float inv = sinv;
    float4 w0 = wr[threadIdx.x], w1 = wr[threadIdx.x + 256];
    __half2* orow = (__half2*)(out + (size_t)row * DD);
    orow[2*threadIdx.x]       = __floats2half2_rn(v0.x*inv*w0.x, v0.y*inv*w0.y);
    orow[2*threadIdx.x + 1]   = __floats2half2_rn(v0.z*inv*w0.z, v0.w*inv*w0.w);
    orow[512 + 2*threadIdx.x] = __floats2half2_rn(v1.x*inv*w1.x, v1.y*inv*w1.y);
    orow[513 + 2*threadIdx.x] = __floats2half2_rn(v1.z*inv*w1.z, v1.w*inv*w1.w);
}

// ---------------- fp32 -> fp16 conversion ----------------
__global__ __launch_bounds__(256) void f2h_kernel(
    const float* __restrict__ in, __half* __restrict__ out)
{
    size_t i = (size_t)blockIdx.x * 256 + threadIdx.x;
    float4 v = ((const float4*)in)[i];
    ((__half2*)out)[2*i]   = __floats2half2_rn(v.x, v.y);
    ((__half2*)out)[2*i+1] = __floats2half2_rn(v.z, v.w);
}

// ---------------- gate/up weights -> interleaved fp16 (16-row granules) ----------------
// out rows: [32j..32j+15] = wg[16j..16j+15], [32j+16..32j+31] = wu[16j..16j+15]
__global__ __launch_bounds__(256) void f2h_ilv_kernel(
    const float* __restrict__ wg, const float* __restrict__ wu, __half* __restrict__ out)
{
    size_t i = (size_t)blockIdx.x * 256 + threadIdx.x;
    int c4 = (int)(i % (DD/4));
    int r  = (int)(i / (DD/4));
    int rg = 32*(r >> 4) + (r & 15);
    float4 gv = ((const float4*)wg)[i];
    float4 uv = ((const float4*)wu)[i];
    __half2* og = (__half2*)(out + (size_t)rg * DD + c4*4);
    og[0] = __floats2half2_rn(gv.x, gv.y);
    og[1] = __floats2half2_rn(gv.z, gv.w);
    __half2* ou = (__half2*)(out + (size_t)(rg + 16) * DD + c4*4);
    ou[0] = __floats2half2_rn(uv.x, uv.y);
    ou[1] = __floats2half2_rn(uv.z, uv.w);
}

// ---------------- bias concat (q|k|v) ----------------
__global__ void bias_concat_kernel(
    const float* __restrict__ bq, const float* __restrict__ bk,
    const float* __restrict__ bv, float* __restrict__ o)
{
    int i = blockIdx.x * 256 + threadIdx.x;
    if (i < 2048) o[i] = bq[i];
    else if (i < 2304) o[i] = bk[i - 2048];
    else if (i < QKVN) o[i] = bv[i - 2304];
}

// ---------------- RoPE cos/sin table ----------------
__global__ __launch_bounds__(256) void rope_table_kernel(float2* __restrict__ tab)
{
    int idx = blockIdx.x * 256 + threadIdx.x;   // SS*64
    int pos = idx >> 6, d = idx & 63;
    float inv = exp2f(-(float)d * (13.287712379549449f / 64.0f));
    float fr  = (float)pos * inv;
    float c, sn;
    __sincosf(fr, &sn, &c);
    tab[idx] = make_float2(c, sn);
}

// ---------------- RoPE for K (in place, table-based) ----------------
__global__ __launch_bounds__(256) void rope_k_kernel(
    __half* __restrict__ buf, const float2* __restrict__ tab)
{
    int idx = blockIdx.x * 256 + threadIdx.x;   // MM*KVH*64
    int d   = idx & 63;
    int t   = idx >> 6;
    int hh  = t % KVH;
    int m   = t / KVH;
    int pos = m & (SS - 1);
    float2 cs = tab[pos * 64 + d];
    __half* p = buf + (size_t)m * QKVN + 2048 + hh * HDIM + d;
    float x1 = __half2float(p[0]), x2 = __half2float(p[64]);
    p[0]  = __float2half_rn(x1 * cs.x - x2 * cs.y);
    p[64] = __float2half_rn(x2 * cs.x + x1 * cs.y);
}

// ---------------- Flash attention (causal, GQA), fp16 mma, Q-rope fused ----------------
#define FQP 136
#define FPP 72
#define FA_SMEM ((128*FQP + 4*64*FQP + 128*FPP) * 2)   // Q + 2-stage K/V + P

__global__ __launch_bounds__(256, 1) void flash_mma_kernel(
    const __half* __restrict__ QKV, const float2* __restrict__ rope,
    __half* __restrict__ O)
{
    extern __shared__ __half smh[];
    __half* Qs  = smh;                       // [128][136]
    __half* Kst = Qs + 128*FQP;              // [2][64][136]
    __half* Vst = Kst + 2*64*FQP;            // [2][64][136]
    __half* Ps  = Vst + 2*64*FQP;            // [128][72]
    const uint32_t sbK = smem_u32(Kst);
    const uint32_t sbV = smem_u32(Vst);

    const int qt = blockIdx.x, bh = blockIdx.y;
    const int b = bh >> 4, h = bh & 15, kvh = h >> 3;
    const int tid = threadIdx.x, lane = tid & 31, wid = tid >> 5;
    const int gi = lane >> 2, tg = lane & 3;
    const float scale = 0.088388347648318447f;

    // Q tile with fused RoPE: each thread handles 8 low cols + 8 mirrored cols
    for (int f = tid; f < 1024; f += 256) {
        int r = f >> 3, c4 = f & 7;          // cols c4*8 (d<64) and +64
        const __half* qp = QKV + (size_t)(b*SS + qt*128 + r) * QKVN + h*HDIM + c4*8;
        uint4 lo4 = *(const uint4*)qp;
        uint4 hi4 = *(const uint4*)(qp + 64);
        const float2* tb = rope + (qt*128 + r) * 64 + c4*8;
        __half2* loh = (__half2*)&lo4;
        __half2* hih = (__half2*)&hi4;
        uint4 olo, ohi;
        __half2* oloh = (__half2*)&olo;
        __half2* ohih = (__half2*)&ohi;
        #pragma unroll
        for (int i = 0; i < 4; i++) {
            float2 x1 = __half22float2(loh[i]);
            float2 x2 = __half22float2(hih[i]);
            float2 c0 = tb[2*i], c1 = tb[2*i+1];
            oloh[i] = __floats2half2_rn(x1.x*c0.x - x2.x*c0.y, x1.y*c1.x - x2.y*c1.y);
            ohih[i] = __floats2half2_rn(x2.x*c0.x + x1.x*c0.y, x2.y*c1.x + x1.y*c1.y);
        }
        *(uint4*)(Qs + r*FQP + c4*8)      = olo;
        *(uint4*)(Qs + r*FQP + c4*8 + 64) = ohi;
    }

    auto load_kv = [&](int st, int kt) {
        const uint32_t kb = sbK + (uint32_t)st * (64*FQP*2);
        const uint32_t vb = sbV + (uint32_t)st * (64*FQP*2);
        #pragma unroll
        for (int u = 0; u < 4; u++) {
            int f = tid + u * 256;
            int r = f >> 4, c8 = f & 15;
            size_t base = (size_t)(b*SS + kt*64 + r) * QKVN + kvh * HDIM;
            cp16(kb + (uint32_t)(r * (FQP*2) + c8 * 16), QKV + base + 2048 + c8*8);
            cp16(vb + (uint32_t)(r * (FQP*2) + c8 * 16), QKV + base + 2304 + c8*8);
        }
        cp_commit();
    };

    float oacc[16][4];
    #pragma unroll
    for (int i = 0; i < 16; i++)
        #pragma unroll
        for (int e = 0; e < 4; e++) oacc[i][e] = 0.f;
    float mrow[2] = {-1e30f, -1e30f}, lrow[2] = {0.f, 0.f};

    const int r0 = wid*16 + gi;
    const int kmax = 2*qt + 2;

    load_kv(0, 0);

    for (int kt = 0; kt < kmax; kt++) {
        __syncthreads();
        if (kt + 1 < kmax) {
            load_kv((kt + 1) & 1, kt + 1);
            asm volatile("cp.async.wait_group 1;" ::: "memory");
        } else {
            asm volatile("cp.async.wait_group 0;" ::: "memory");
        }
        __syncthreads();

        if (kt*64 > qt*128 + wid*16 + 15) continue;

        const __half* Ks = Kst + (kt & 1) * 64*FQP;
        const __half* Vs = Vst + (kt & 1) * 64*FQP;

        float sa[8][4];
        #pragma unroll
        for (int nt = 0; nt < 8; nt++)
            #pragma unroll
            for (int e = 0; e < 4; e++) sa[nt][e] = 0.f;
        #pragma unroll
        for (int ks = 0; ks < 8; ks++) {
            const int k0 = ks*16 + 2*tg;
            uint32_t a[4];
            a[0] = *(const uint32_t*)(Qs + r0*FQP + k0);
            a[1] = *(const uint32_t*)(Qs + (r0+8)*FQP + k0);
            a[2] = *(const uint32_t*)(Qs + r0*FQP + k0 + 8);
            a[3] = *(const uint32_t*)(Qs + (r0+8)*FQP + k0 + 8);
            #pragma unroll
            for (int nt = 0; nt < 8; nt++) {
                const int n = nt*8 + gi;
                uint32_t bb[2];
                bb[0] = *(const uint32_t*)(Ks + n*FQP + k0);
                bb[1] = *(const uint32_t*)(Ks + n*FQP + k0 + 8);
                mma_f16(sa[nt], a, bb);
            }
        }
        #pragma unroll
        for (int nt = 0; nt < 8; nt++)
            #pragma unroll
            for (int e = 0; e < 4; e++) sa[nt][e] *= scale;
        if (kt >= 2*qt) {
            const int qr0 = qt*128 + r0, qr1 = qr0 + 8;
            #pragma unroll
            for (int nt = 0; nt < 8; nt++) {
                int kc = kt*64 + nt*8 + 2*tg;
                if (kc     > qr0) sa[nt][0] = -1e30f;
                if (kc + 1 > qr0) sa[nt][1] = -1e30f;
                if (kc     > qr1) sa[nt][2] = -1e30f;
                if (kc + 1 > qr1) sa[nt][3] = -1e30f;
            }
        }

        float mx0 = -1e30f, mx1 = -1e30f;
        #pragma unroll
        for (int nt = 0; nt < 8; nt++) {
            mx0 = fmaxf(mx0, fmaxf(sa[nt][0], sa[nt][1]));
            mx1 = fmaxf(mx1, fmaxf(sa[nt][2], sa[nt][3]));
        }
        mx0 = fmaxf(mx0, __shfl_xor_sync(0xffffffffu, mx0, 1));
        mx0 = fmaxf(mx0, __shfl_xor_sync(0xffffffffu, mx0, 2));
        mx1 = fmaxf(mx1, __shfl_xor_sync(0xffffffffu, mx1, 1));
        mx1 = fmaxf(mx1, __shfl_xor_sync(0xffffffffu, mx1, 2));
        const float mn0 = fmaxf(mrow[0], mx0), mn1 = fmaxf(mrow[1], mx1);
        const float cr0 = __expf(mrow[0] - mn0), cr1 = __expf(mrow[1] - mn1);
        float s0 = 0.f, s1 = 0.f;
        #pragma unroll
        for (int nt = 0; nt < 8; nt++) {
            __half2 p0 = __floats2half2_rn(__expf(sa[nt][0] - mn0), __expf(sa[nt][1] - mn0));
            __half2 p1 = __floats2half2_rn(__expf(sa[nt][2] - mn1), __expf(sa[nt][3] - mn1));
            float2 p0f = __half22float2(p0), p1f = __half22float2(p1);
            s0 += p0f.x + p0f.y;
            s1 += p1f.x + p1f.y;
            *(__half2*)(Ps + r0*FPP + nt*8 + 2*tg)     = p0;
            *(__half2*)(Ps + (r0+8)*FPP + nt*8 + 2*tg) = p1;
        }
        s0 += __shfl_xor_sync(0xffffffffu, s0, 1);
        s0 += __shfl_xor_sync(0xffffffffu, s0, 2);
        s1 += __shfl_xor_sync(0xffffffffu, s1, 1);
        s1 += __shfl_xor_sync(0xffffffffu, s1, 2);
        lrow[0] = lrow[0]*cr0 + s0;
        lrow[1] = lrow[1]*cr1 + s1;
        mrow[0] = mn0; mrow[1] = mn1;
        #pragma unroll
        for (int nt = 0; nt < 16; nt++) {
            oacc[nt][0] *= cr0; oacc[nt][1] *= cr0;
            oacc[nt][2] *= cr1; oacc[nt][3] *= cr1;
        }
        __syncwarp();

        #pragma unroll
        for (int ks = 0; ks < 4; ks++) {
            const int k0 = ks*16 + 2*tg;
            uint32_t a[4];
            a[0] = *(const uint32_t*)(Ps + r0*FPP + k0);
            a[1] = *(const uint32_t*)(Ps + (r0+8)*FPP + k0);
            a[2] = *(const uint32_t*)(Ps + r0*FPP + k0 + 8);
            a[3] = *(const uint32_t*)(Ps + (r0+8)*FPP + k0 + 8);
            #pragma unroll
            for (int ntp = 0; ntp < 8; ntp++) {
                int kvrow = ks*16 + (lane & 15);
                int dcol  = (ntp*2 + (lane >> 4)) * 8;
                uint32_t addr = smem_u32(Vs + kvrow*FQP + dcol);
                uint32_t b0, b1, b2, b3;
                asm volatile(
                    "ldmatrix.sync.aligned.m8n8.x4.trans.shared.b16 {%0,%1,%2,%3}, [%4];"
                    : "=r"(b0), "=r"(b1), "=r"(b2), "=r"(b3) : "r"(addr));
                uint32_t bb0[2] = {b0, b1}, bb1[2] = {b2, b3};
                mma_f16(oacc[2*ntp],     a, bb0);
                mma_f16(oacc[2*ntp + 1], a, bb1);
            }
        }
    }

    const float inv0 = 1.0f / lrow[0], inv1 = 1.0f / lrow[1];
    __half* op0 = O + (size_t)(b*SS + qt*128 + r0)     * DD + h*HDIM + 2*tg;
    __half* op1 = O + (size_t)(b*SS + qt*128 + r0 + 8) * DD + h*HDIM + 2*tg;
    #pragma unroll
    for (int nt = 0; nt < 16; nt++) {
        *(__half2*)(op0 + nt*8) = __floats2half2_rn(oacc[nt][0]*inv0, oacc[nt][1]*inv0);
        *(__half2*)(op1 + nt*8) = __floats2half2_rn(oacc[nt][2]*inv1, oacc[nt][3]*inv1);
    }
}

// ---------------- launch ----------------
extern "C" void kernel_launch(void* const* d_in, const int* in_sizes, int n_in,
                              void* d_out, int out_size)
{
    (void)in_sizes; (void)n_in; (void)out_size;
    const float* x   = (const float*)d_in[0];
    const float* ln1 = (const float*)d_in[2];
    const float* wq  = (const float*)d_in[3];
    const float* bq  = (const float*)d_in[4];
    const float* wk  = (const float*)d_in[5];
    const float* bk  = (const float*)d_in[6];
    const float* wv  = (const float*)d_in[7];
    const float* bv  = (const float*)d_in[8];
    const float* wo  = (const float*)d_in[9];
    const float* ln2 = (const float*)d_in[10];
    const float* wg  = (const float*)d_in[11];
    const float* wu  = (const float*)d_in[12];
    const float* wd  = (const float*)d_in[13];
    float* out = (float*)d_out;

    __half *h, *qkv, *attn, *g, *act;
    __half *rwqkv, *rwo, *rwgu, *rwd;
    float *h2, *bqkv;
    float2 *rope;
    cudaGetSymbolAddress((void**)&h,     g_h);
    cudaGetSymbolAddress((void**)&qkv,   g_qkv);
    cudaGetSymbolAddress((void**)&attn,  g_attn);
    cudaGetSymbolAddress((void**)&h2,    g_h2);
    cudaGetSymbolAddress((void**)&g,     g_g);
    cudaGetSymbolAddress((void**)&act,   g_act);
    cudaGetSymbolAddress((void**)&rwqkv, g_wqkv);
    cudaGetSymbolAddress((void**)&rwo,   g_wo);
    cudaGetSymbolAddress((void**)&rwgu,  g_wgu);
    cudaGetSymbolAddress((void**)&rwd,   g_wd);
    cudaGetSymbolAddress((void**)&bqkv,  g_bqkv);
    cudaGetSymbolAddress((void**)&rope,  g_rope);

    cudaFuncSetAttribute((const void*)hgemm_kernel<1,__half>, cudaFuncAttributeMaxDynamicSharedMemorySize, GEMM_SMEM);
    cudaFuncSetAttribute((const void*)hgemm_kernel<2,float>,  cudaFuncAttributeMaxDynamicSharedMemorySize, GEMM_SMEM);
    cudaFuncSetAttribute((const void*)hgemm_kernel<3,__half>, cudaFuncAttributeMaxDynamicSharedMemorySize, GEMM_SMEM);
    cudaFuncSetAttribute((const void*)flash_mma_kernel, cudaFuncAttributeMaxDynamicSharedMemorySize, FA_SMEM);

    // 0. weights -> fp16, rope table, bias concat
    rope_table_kernel<<<(SS*64)/256, 256>>>(rope);
    f2h_kernel<<<(DD*DD/4)/256, 256>>>(wq, rwqkv);
    f2h_kernel<<<(256*DD/4)/256, 256>>>(wk, rwqkv + 2048*DD);
    f2h_kernel<<<(256*DD/4)/256, 256>>>(wv, rwqkv + 2304*DD);
    f2h_kernel<<<(DD*DD/4)/256, 256>>>(wo, rwo);
    f2h_ilv_kernel<<<(II*DD/4)/256, 256>>>(wg, wu, rwgu);
    f2h_kernel<<<(DD*II/4)/256, 256>>>(wd, rwd);
    bias_concat_kernel<<<10, 256>>>(bq, bk, bv, bqkv);

    // 1. h = rmsnorm(x, ln1) -> half
    rmsnorm_kernel<<<MM, 256>>>(x, ln1, h);

    // 2. fused qkv projection (+bias); 128x128 tiles, 2 CTAs/SM
    hgemm_kernel<1,__half><<<dim3(QKVN/128, MM/128), 256, GEMM_SMEM>>>(h, rwqkv, bqkv, qkv, MM, QKVN, DD);

    // 3. RoPE for K only (Q rope fused into attention)
    rope_k_kernel<<<(MM*KVH*64)/256, 256>>>(qkv, rope);

    // 4. attention (Q-rope applied during Q-tile load)
    flash_mma_kernel<<<dim3(SS/128, BB*HH), 256, FA_SMEM>>>(qkv, rope, attn);

    // 5. h2 = x + attn @ wo^T (fp32)
    hgemm_kernel<2,float><<<dim3(DD/128, MM/128), 256, GEMM_SMEM>>>(attn, rwo, x, h2, MM, DD, DD);

    // 6. g = rmsnorm(h2, ln2) -> half
    rmsnorm_kernel<<<MM, 256>>>(h2, ln2, g);

    // 7. fused MLP gate/up + silu
    hgemm_kernel<3,__half><<<dim3(2*II/128, MM/128), 256, GEMM_SMEM>>>(g, rwgu, nullptr, act, MM, II, DD);

    // 8. out = h2 + act @ wd^T (fp32)
    hgemm_kernel<2,float><<<dim3(DD/128, MM/128), 256, GEMM_SMEM>>>(act, rwd, h2, out, MM, DD, II);
}

// round 15
// speedup vs baseline: 1.1716x; 1.0177x over previous
#include <cuda_runtime.h>
#include <cuda_fp16.h>
#include <math.h>
#include <stdint.h>

// Problem constants
#define BB 2
#define SS 2048
#define DD 2048
#define HH 16
#define KVH 2
#define HDIM 128
#define II 5504
#define MM (BB*SS)          // 4096
#define QKVN 2560           // 2048 q + 256 k + 256 v

// ---------------- scratch (device globals; allocation-free) ----------------
__device__ __half g_h   [MM*DD];
__device__ __half g_qkv [MM*QKVN];
__device__ __half g_attn[MM*DD];
__device__ float  g_h2  [MM*DD];
__device__ __half g_g   [MM*DD];
__device__ __half g_act [MM*II];          // silu(gate)*up
__device__ __half g_wqkv[QKVN*DD];
__device__ __half g_wo[DD*DD];
__device__ __half g_wgu[2*II*DD];         // interleaved gate/up weights (16-row granules)
__device__ __half g_wd[DD*II];
__device__ float  g_bqkv[QKVN];
__device__ float2 g_rope[SS*64];          // (cos, sin) per (pos, d)

// ---------------- small helpers ----------------
__inline__ __device__ float warpReduceSum(float v) {
    #pragma unroll
    for (int m = 16; m; m >>= 1) v += __shfl_xor_sync(0xffffffffu, v, m);
    return v;
}
__device__ __forceinline__ uint32_t smem_u32(const void* p) {
    uint32_t a;
    asm("{ .reg .u64 t; cvta.to.shared.u64 t, %1; cvt.u32.u64 %0, t; }" : "=r"(a) : "l"(p));
    return a;
}
__device__ __forceinline__ void cp16(uint32_t s, const void* g) {
    asm volatile("cp.async.cg.shared.global [%0], [%1], 16;" :: "r"(s), "l"(g));
}
__device__ __forceinline__ void cp_commit() {
    asm volatile("cp.async.commit_group;" ::: "memory");
}
__device__ __forceinline__ void mma_f16(float* c, const uint32_t* a, const uint32_t* b) {
    asm volatile(
        "mma.sync.aligned.m16n8k16.row.col.f32.f16.f16.f32 "
        "{%0,%1,%2,%3}, {%4,%5,%6,%7}, {%8,%9}, {%0,%1,%2,%3};"
        : "+f"(c[0]), "+f"(c[1]), "+f"(c[2]), "+f"(c[3])
        : "r"(a[0]), "r"(a[1]), "r"(a[2]), "r"(a[3]), "r"(b[0]), "r"(b[1]));
}
__device__ __forceinline__ void ldm_x4(uint32_t* r, uint32_t addr) {
    asm volatile("ldmatrix.sync.aligned.m8n8.x4.shared.b16 {%0,%1,%2,%3}, [%4];"
        : "=r"(r[0]), "=r"(r[1]), "=r"(r[2]), "=r"(r[3]) : "r"(addr));
}
__device__ __forceinline__ float silu_f(float x) {
    return x / (1.f + __expf(-x));
}

// ---------------- FP16 mma.sync GEMM: C = A(MxK) @ B(NxK)^T ----------------
// CTA tile 128x128x64, warp tile 64x32 (8 warps, 2 M x 4 N), 3-stage cp.async,
// ldmatrix.x4, pitch 72 halves. 110.6KB smem -> 2 CTAs/SM.
#define GPITCH_B  144
#define A_TILE_B  (128*GPITCH_B)
#define B_TILE_B  (128*GPITCH_B)
#define STAGE_B   (A_TILE_B + B_TILE_B)
#define GEMM_SMEM (3*STAGE_B)              // 110592

// MODE 0: plain->half, MODE 1: +bias[col]->half, MODE 2: +aux[row*N+col]->float,
// MODE 3: silu-fused MLP (B interleaved gate/up, 16-row granules) -> half
template<int MODE, typename CT>
__global__ __launch_bounds__(256, 2) void hgemm_kernel(
    const __half* __restrict__ A, const __half* __restrict__ Bw,
    const float* __restrict__ aux, CT* __restrict__ C,
    int M, int N, int K)
{
    extern __shared__ __half smh[];
    const uint32_t sb = smem_u32(smh);
    const int tid  = threadIdx.x;
    const int lane = tid & 31;
    const int wid  = tid >> 5;
    const int wm   = wid >> 2;
    const int wn   = wid & 3;
    const int gi   = lane >> 2, tg = lane & 3;
    const int bn = blockIdx.x, bm = blockIdx.y;
    const __half* Ab = A  + (size_t)bm * 128 * K;
    const __half* Bb = Bw + (size_t)bn * 128 * K;

    const int nk = K >> 6;

    const int lrow = tid >> 3, lc = tid & 7;
    auto load_stage = [&](int stage, int kt) {
        const uint32_t as = sb + (uint32_t)stage * STAGE_B;
        const uint32_t bs = as + A_TILE_B;
        const __half* Asrc = Ab + (size_t)kt * 64;
        const __half* Bsrc = Bb + (size_t)kt * 64;
        #pragma unroll
        for (int u = 0; u < 4; u++) {
            int row = lrow + u * 32;
            cp16(as + (uint32_t)(row * GPITCH_B + lc * 16),
                 Asrc + (size_t)row * K + lc * 8);
        }
        #pragma unroll
        for (int u = 0; u < 4; u++) {
            int row = lrow + u * 32;
            cp16(bs + (uint32_t)(row * GPITCH_B + lc * 16),
                 Bsrc + (size_t)row * K + lc * 8);
        }
        cp_commit();
    };

    float acc[4][4][4];
    #pragma unroll
    for (int i = 0; i < 4; i++)
        #pragma unroll
        for (int j = 0; j < 4; j++)
            #pragma unroll
            for (int e = 0; e < 4; e++) acc[i][j][e] = 0.f;

    load_stage(0, 0);
    if (nk > 1) load_stage(1, 1);

    const uint32_t a_off = (uint32_t)((lane & 15) * GPITCH_B + ((lane >> 4) << 4));
    const uint32_t b_off = (uint32_t)(((lane & 7) + ((lane >> 4) << 3)) * GPITCH_B
                                      + (((lane >> 3) & 1) << 4));

    int rd = 0, wr = 2;
    for (int kt = 0; kt < nk; kt++) {
        if (kt + 1 < nk)
            asm volatile("cp.async.wait_group 1;" ::: "memory");
        else
            asm volatile("cp.async.wait_group 0;" ::: "memory");
        __syncthreads();
        if (kt + 2 < nk) load_stage(wr, kt + 2);

        const uint32_t as = sb + (uint32_t)rd * STAGE_B;
        const uint32_t bs = as + A_TILE_B;
        const uint32_t a_base = as + (uint32_t)(wm * 64) * GPITCH_B + a_off;
        const uint32_t b_base = bs + (uint32_t)(wn * 32) * GPITCH_B + b_off;

        #pragma unroll
        for (int kk = 0; kk < 4; kk++) {
            const uint32_t k0b = kk * 32;
            uint32_t a[4][4], b[4][2];
            #pragma unroll
            for (int mt = 0; mt < 4; mt++)
                ldm_x4(a[mt], a_base + (uint32_t)(mt * 16) * GPITCH_B + k0b);
            #pragma unroll
            for (int nb = 0; nb < 2; nb++) {
                uint32_t r[4];
                ldm_x4(r, b_base + (uint32_t)(nb * 16) * GPITCH_B + k0b);
                b[2*nb][0] = r[0]; b[2*nb][1] = r[1];
                b[2*nb+1][0] = r[2]; b[2*nb+1][1] = r[3];
            }
            #pragma unroll
            for (int mt = 0; mt < 4; mt++)
                #pragma unroll
                for (int nt = 0; nt < 4; nt++)
                    mma_f16(acc[mt][nt], a[mt], b[nt]);
        }
        rd = (rd == 2) ? 0 : rd + 1;
        wr = (wr == 2) ? 0 : wr + 1;
    }

    if (MODE == 3) {
        const int j = bn * 4 + wn;
        #pragma unroll
        for (int mt = 0; mt < 4; mt++) {
            const int r0 = bm * 128 + wm * 64 + mt * 16 + gi;
            #pragma unroll
            for (int jt = 0; jt < 2; jt++) {
                const int c = j * 16 + jt * 8 + 2*tg;
                float a00 = silu_f(acc[mt][jt][0]) * acc[mt][jt+2][0];
                float a01 = silu_f(acc[mt][jt][1]) * acc[mt][jt+2][1];
                float a10 = silu_f(acc[mt][jt][2]) * acc[mt][jt+2][2];
                float a11 = silu_f(acc[mt][jt][3]) * acc[mt][jt+2][3];
                *(__half2*)((__half*)C + (size_t)r0 * N + c) = __floats2half2_rn(a00, a01);
                *(__half2*)((__half*)C + (size_t)(r0 + 8) * N + c) = __floats2half2_rn(a10, a11);
            }
        }
        return;
    }
    #pragma unroll
    for (int mt = 0; mt < 4; mt++) {
        const int r0 = bm * 128 + wm * 64 + mt * 16 + gi;
        #pragma unroll
        for (int nt = 0; nt < 4; nt++) {
            const int c = bn * 128 + wn * 32 + nt * 8 + 2*tg;
            float v00 = acc[mt][nt][0], v01 = acc[mt][nt][1];
            float v10 = acc[mt][nt][2], v11 = acc[mt][nt][3];
            if (MODE == 1) {
                float bx = aux[c], by = aux[c + 1];
                v00 += bx; v01 += by; v10 += bx; v11 += by;
            }
            if (MODE == 2) {
                const float2 a0 = *(const float2*)(aux + (size_t)r0 * N + c);
                const float2 a1 = *(const float2*)(aux + (size_t)(r0 + 8) * N + c);
                v00 += a0.x; v01 += a0.y; v10 += a1.x; v11 += a1.y;
                *(float2*)((float*)C + (size_t)r0 * N + c) = make_float2(v00, v01);
                *(float2*)((float*)C + (size_t)(r0 + 8) * N + c) = make_float2(v10, v11);
            } else {
                *(__half2*)((__half*)C + (size_t)r0 * N + c) = __floats2half2_rn(v00, v01);
                *(__half2*)((__half*)C + (size_t)(r0 + 8) * N + c) = __floats2half2_rn(v10, v11);
            }
        }
    }
}

// ---------------- RMSNorm: fp32 in -> half out ----------------
__global__ __launch_bounds__(256) void rmsnorm_kernel(
    const float* __restrict__ x, const float* __restrict__ w, __half* __restrict__ out)
{
    int row = blockIdx.x;
    const float4* xr = (const float4*)(x + (size_t)row * DD);
    const float4* wr = (const float4*)w;
    float4 v0 = xr[threadIdx.x];
    float4 v1 = xr[threadIdx.x + 256];
    float s = v0.x*v0.x + v0.y*v0.y + v0.z*v0.z + v0.w*v0.w
            + v1.x*v1.x + v1.y*v1.y + v1.z*v1.z + v1.w*v1.w;
    s = warpReduceSum(s);
    __shared__ float smw[8];
    __shared__ float sinv;
    if ((threadIdx.x & 31) == 0) smw[threadIdx.x >> 5] = s;
    __syncthreads();
    if (threadIdx.x == 0) {
        float t = 0.f;
        #pragma unroll
        for (int i = 0; i < 8; i++) t += smw[i];
        sinv = rsqrtf(t * (1.0f / DD) + 1e-6f);
    }
    __syncthreads();
    float inv = sinv;
    float4 w0 = wr[threadIdx.x], w1 = wr[threadIdx.x + 256];
    __half2* orow = (__half2*)(out + (size_t)row * DD);
    orow[2*threadIdx.x]       = __floats2half2_rn(v0.x*inv*w0.x, v0.y*inv*w0.y);
    orow[2*threadIdx.x + 1]   = __floats2half2_rn(v0.z*inv*w0.z, v0.w*inv*w0.w);
    orow[512 + 2*threadIdx.x] = __floats2half2_rn(v1.x*inv*w1.x, v1.y*inv*w1.y);
    orow[513 + 2*threadIdx.x] = __floats2half2_rn(v1.z*inv*w1.z, v1.w*inv*w1.w);
}

// ---------------- fp32 -> fp16 conversion ----------------
__global__ __launch_bounds__(256) void f2h_kernel(
    const float* __restrict__ in, __half* __restrict__ out)
{
    size_t i = (size_t)blockIdx.x * 256 + threadIdx.x;
    float4 v = ((const float4*)in)[i];
    ((__half2*)out)[2*i]   = __floats2half2_rn(v.x, v.y);
    ((__half2*)out)[2*i+1] = __floats2half2_rn(v.z, v.w);
}

// ---------------- gate/up weights -> interleaved fp16 (16-row granules) ----------------
__global__ __launch_bounds__(256) void f2h_ilv_kernel(
    const float* __restrict__ wg, const float* __restrict__ wu, __half* __restrict__ out)
{
    size_t i = (size_t)blockIdx.x * 256 + threadIdx.x;
    int c4 = (int)(i % (DD/4));
    int r  = (int)(i / (DD/4));
    int rg = 32*(r >> 4) + (r & 15);
    float4 gv = ((const float4*)wg)[i];
    float4 uv = ((const float4*)wu)[i];
    __half2* og = (__half2*)(out + (size_t)rg * DD + c4*4);
    og[0] = __floats2half2_rn(gv.x, gv.y);
    og[1] = __floats2half2_rn(gv.z, gv.w);
    __half2* ou = (__half2*)(out + (size_t)(rg + 16) * DD + c4*4);
    ou[0] = __floats2half2_rn(uv.x, uv.y);
    ou[1] = __floats2half2_rn(uv.z, uv.w);
}

// ---------------- bias concat (q|k|v) ----------------
__global__ void bias_concat_kernel(
    const float* __restrict__ bq, const float* __restrict__ bk,
    const float* __restrict__ bv, float* __restrict__ o)
{
    int i = blockIdx.x * 256 + threadIdx.x;
    if (i < 2048) o[i] = bq[i];
    else if (i < 2304) o[i] = bk[i - 2048];
    else if (i < QKVN) o[i] = bv[i - 2304];
}

// ---------------- RoPE cos/sin table ----------------
__global__ __launch_bounds__(256) void rope_table_kernel(float2* __restrict__ tab)
{
    int idx = blockIdx.x * 256 + threadIdx.x;   // SS*64
    int pos = idx >> 6, d = idx & 63;
    float inv = exp2f(-(float)d * (13.287712379549449f / 64.0f));
    float fr  = (float)pos * inv;
    float c, sn;
    __sincosf(fr, &sn, &c);
    tab[idx] = make_float2(c, sn);
}

// ---------------- RoPE for K (in place, table-based) ----------------
__global__ __launch_bounds__(256) void rope_k_kernel(
    __half* __restrict__ buf, const float2* __restrict__ tab)
{
    int idx = blockIdx.x * 256 + threadIdx.x;   // MM*KVH*64
    int d   = idx & 63;
    int t   = idx >> 6;
    int hh  = t % KVH;
    int m   = t / KVH;
    int pos = m & (SS - 1);
    float2 cs = tab[pos * 64 + d];
    __half* p = buf + (size_t)m * QKVN + 2048 + hh * HDIM + d;
    float x1 = __half2float(p[0]), x2 = __half2float(p[64]);
    p[0]  = __float2half_rn(x1 * cs.x - x2 * cs.y);
    p[64] = __float2half_rn(x2 * cs.x + x1 * cs.y);
}

// ---------------- Flash attention (causal, GQA), fp16 mma, Q-rope fused ----------------
// Paired q-tiles: CTA x handles qt = x and qt = NQT-1-x -> uniform 34 tiles/CTA.
#define FQP 136
#define FPP 72
#define NQT (SS/128)
#define FA_SMEM ((128*FQP + 4*64*FQP + 128*FPP) * 2)   // Q + 2-stage K/V + P

__global__ __launch_bounds__(256, 1) void flash_mma_kernel(
    const __half* __restrict__ QKV, const float2* __restrict__ rope,
    __half* __restrict__ O)
{
    extern __shared__ __half smh[];
    __half* Qs  = smh;                       // [128][136]
    __half* Kst = Qs + 128*FQP;              // [2][64][136]
    __half* Vst = Kst + 2*64*FQP;            // [2][64][136]
    __half* Ps  = Vst + 2*64*FQP;            // [128][72]
    const uint32_t sbK = smem_u32(Kst);
    const uint32_t sbV = smem_u32(Vst);

    const int bh = blockIdx.y;
    const int b = bh >> 4, h = bh & 15, kvh = h >> 3;
    const int tid = threadIdx.x, lane = tid & 31, wid = tid >> 5;
    const int gi = lane >> 2, tg = lane & 3;
    const float scale = 0.088388347648318447f;
    const int r0 = wid*16 + gi;

    #pragma unroll 1
    for (int pass = 0; pass < 2; pass++) {
        const int qt = pass ? (NQT - 1 - (int)blockIdx.x) : (int)blockIdx.x;
        if (pass) __syncthreads();   // all warps done reading Qs/Ps from pass 0

        // Q tile with fused RoPE
        for (int f = tid; f < 1024; f += 256) {
            int r = f >> 3, c4 = f & 7;
            const __half* qp = QKV + (size_t)(b*SS + qt*128 + r) * QKVN + h*HDIM + c4*8;
            uint4 lo4 = *(const uint4*)qp;
            uint4 hi4 = *(const uint4*)(qp + 64);
            const float2* tb = rope + (qt*128 + r) * 64 + c4*8;
            __half2* loh = (__half2*)&lo4;
            __half2* hih = (__half2*)&hi4;
            uint4 olo, ohi;
            __half2* oloh = (__half2*)&olo;
            __half2* ohih = (__half2*)&ohi;
            #pragma unroll
            for (int i = 0; i < 4; i++) {
                float2 x1 = __half22float2(loh[i]);
                float2 x2 = __half22float2(hih[i]);
                float2 c0 = tb[2*i], c1 = tb[2*i+1];
                oloh[i] = __floats2half2_rn(x1.x*c0.x - x2.x*c0.y, x1.y*c1.x - x2.y*c1.y);
                ohih[i] = __floats2half2_rn(x2.x*c0.x + x1.x*c0.y, x2.y*c1.x + x1.y*c1.y);
            }
            *(uint4*)(Qs + r*FQP + c4*8)      = olo;
            *(uint4*)(Qs + r*FQP + c4*8 + 64) = ohi;
        }

        auto load_kv = [&](int st, int kt) {
            const uint32_t kb = sbK + (uint32_t)st * (64*FQP*2);
            const uint32_t vb = sbV + (uint32_t)st * (64*FQP*2);
            #pragma unroll
            for (int u = 0; u < 4; u++) {
                int f = tid + u * 256;
                int r = f >> 4, c8 = f & 15;
                size_t base = (size_t)(b*SS + kt*64 + r) * QKVN + kvh * HDIM;
                cp16(kb + (uint32_t)(r * (FQP*2) + c8 * 16), QKV + base + 2048 + c8*8);
                cp16(vb + (uint32_t)(r * (FQP*2) + c8 * 16), QKV + base + 2304 + c8*8);
            }
            cp_commit();
        };

        float oacc[16][4];
        #pragma unroll
        for (int i = 0; i < 16; i++)
            #pragma unroll
            for (int e = 0; e < 4; e++) oacc[i][e] = 0.f;
        float mrow[2] = {-1e30f, -1e30f}, lrow[2] = {0.f, 0.f};

        const int kmax = 2*qt + 2;
        load_kv(0, 0);

        for (int kt = 0; kt < kmax; kt++) {
            __syncthreads();
            if (kt + 1 < kmax) {
                load_kv((kt + 1) & 1, kt + 1);
                asm volatile("cp.async.wait_group 1;" ::: "memory");
            } else {
                asm volatile("cp.async.wait_group 0;" ::: "memory");
            }
            __syncthreads();

            if (kt*64 > qt*128 + wid*16 + 15) continue;

            const __half* Ks = Kst + (kt & 1) * 64*FQP;
            const __half* Vs = Vst + (kt & 1) * 64*FQP;

            float sa[8][4];
            #pragma unroll
            for (int nt = 0; nt < 8; nt++)
                #pragma unroll
                for (int e = 0; e < 4; e++) sa[nt][e] = 0.f;
            #pragma unroll
            for (int ks = 0; ks < 8; ks++) {
                const int k0 = ks*16 + 2*tg;
                uint32_t a[4];
                a[0] = *(const uint32_t*)(Qs + r0*FQP + k0);
                a[1] = *(const uint32_t*)(Qs + (r0+8)*FQP + k0);
                a[2] = *(const uint32_t*)(Qs + r0*FQP + k0 + 8);
                a[3] = *(const uint32_t*)(Qs + (r0+8)*FQP + k0 + 8);
                #pragma unroll
                for (int nt = 0; nt < 8; nt++) {
                    const int n = nt*8 + gi;
                    uint32_t bb[2];
                    bb[0] = *(const uint32_t*)(Ks + n*FQP + k0);
                    bb[1] = *(const uint32_t*)(Ks + n*FQP + k0 + 8);
                    mma_f16(sa[nt], a, bb);
                }
            }
            #pragma unroll
            for (int nt = 0; nt < 8; nt++)
                #pragma unroll
                for (int e = 0; e < 4; e++) sa[nt][e] *= scale;
            if (kt >= 2*qt) {
                const int qr0 = qt*128 + r0, qr1 = qr0 + 8;
                #pragma unroll
                for (int nt = 0; nt < 8; nt++) {
                    int kc = kt*64 + nt*8 + 2*tg;
                    if (kc     > qr0) sa[nt][0] = -1e30f;
                    if (kc + 1 > qr0) sa[nt][1] = -1e30f;
                    if (kc     > qr1) sa[nt][2] = -1e30f;
                    if (kc + 1 > qr1) sa[nt][3] = -1e30f;
                }
            }

            float mx0 = -1e30f, mx1 = -1e30f;
            #pragma unroll
            for (int nt = 0; nt < 8; nt++) {
                mx0 = fmaxf(mx0, fmaxf(sa[nt][0], sa[nt][1]));
                mx1 = fmaxf(mx1, fmaxf(sa[nt][2], sa[nt][3]));
            }
            mx0 = fmaxf(mx0, __shfl_xor_sync(0xffffffffu, mx0, 1));
            mx0 = fmaxf(mx0, __shfl_xor_sync(0xffffffffu, mx0, 2));
            mx1 = fmaxf(mx1, __shfl_xor_sync(0xffffffffu, mx1, 1));
            mx1 = fmaxf(mx1, __shfl_xor_sync(0xffffffffu, mx1, 2));
            const float mn0 = fmaxf(mrow[0], mx0), mn1 = fmaxf(mrow[1], mx1);
            const float cr0 = __expf(mrow[0] - mn0), cr1 = __expf(mrow[1] - mn1);
            float s0 = 0.f, s1 = 0.f;
            #pragma unroll
            for (int nt = 0; nt < 8; nt++) {
                __half2 p0 = __floats2half2_rn(__expf(sa[nt][0] - mn0), __expf(sa[nt][1] - mn0));
                __half2 p1 = __floats2half2_rn(__expf(sa[nt][2] - mn1), __expf(sa[nt][3] - mn1));
                float2 p0f = __half22float2(p0), p1f = __half22float2(p1);
                s0 += p0f.x + p0f.y;
                s1 += p1f.x + p1f.y;
                *(__half2*)(Ps + r0*FPP + nt*8 + 2*tg)     = p0;
                *(__half2*)(Ps + (r0+8)*FPP + nt*8 + 2*tg) = p1;
            }
            s0 += __shfl_xor_sync(0xffffffffu, s0, 1);
            s0 += __shfl_xor_sync(0xffffffffu, s0, 2);
            s1 += __shfl_xor_sync(0xffffffffu, s1, 1);
            s1 += __shfl_xor_sync(0xffffffffu, s1, 2);
            lrow[0] = lrow[0]*cr0 + s0;
            lrow[1] = lrow[1]*cr1 + s1;
            mrow[0] = mn0; mrow[1] = mn1;
            #pragma unroll
            for (int nt = 0; nt < 16; nt++) {
                oacc[nt][0] *= cr0; oacc[nt][1] *= cr0;
                oacc[nt][2] *= cr1; oacc[nt][3] *= cr1;
            }
            __syncwarp();

            #pragma unroll
            for (int ks = 0; ks < 4; ks++) {
                const int k0 = ks*16 + 2*tg;
                uint32_t a[4];
                a[0] = *(const uint32_t*)(Ps + r0*FPP + k0);
                a[1] = *(const uint32_t*)(Ps + (r0+8)*FPP + k0);
                a[2] = *(const uint32_t*)(Ps + r0*FPP + k0 + 8);
                a[3] = *(const uint32_t*)(Ps + (r0+8)*FPP + k0 + 8);
                #pragma unroll
                for (int ntp = 0; ntp < 8; ntp++) {
                    int kvrow = ks*16 + (lane & 15);
                    int dcol  = (ntp*2 + (lane >> 4)) * 8;
                    uint32_t addr = smem_u32(Vs + kvrow*FQP + dcol);
                    uint32_t b0, b1, b2, b3;
                    asm volatile(
                        "ldmatrix.sync.aligned.m8n8.x4.trans.shared.b16 {%0,%1,%2,%3}, [%4];"
                        : "=r"(b0), "=r"(b1), "=r"(b2), "=r"(b3) : "r"(addr));
                    uint32_t bb0[2] = {b0, b1}, bb1[2] = {b2, b3};
                    mma_f16(oacc[2*ntp],     a, bb0);
                    mma_f16(oacc[2*ntp + 1], a, bb1);
                }
            }
        }

        const float inv0 = 1.0f / lrow[0], inv1 = 1.0f / lrow[1];
        __half* op0 = O + (size_t)(b*SS + qt*128 + r0)     * DD + h*HDIM + 2*tg;
        __half* op1 = O + (size_t)(b*SS + qt*128 + r0 + 8) * DD + h*HDIM + 2*tg;
        #pragma unroll
        for (int nt = 0; nt < 16; nt++) {
            *(__half2*)(op0 + nt*8) = __floats2half2_rn(oacc[nt][0]*inv0, oacc[nt][1]*inv0);
            *(__half2*)(op1 + nt*8) = __floats2half2_rn(oacc[nt][2]*inv1, oacc[nt][3]*inv1);
        }
    }
}

// ---------------- launch ----------------
extern "C" void kernel_launch(void* const* d_in, const int* in_sizes, int n_in,
                              void* d_out, int out_size)
{
    (void)in_sizes; (void)n_in; (void)out_size;
    const float* x   = (const float*)d_in[0];
    const float* ln1 = (const float*)d_in[2];
    const float* wq  = (const float*)d_in[3];
    const float* bq  = (const float*)d_in[4];
    const float* wk  = (const float*)d_in[5];
    const float* bk  = (const float*)d_in[6];
    const float* wv  = (const float*)d_in[7];
    const float* bv  = (const float*)d_in[8];
    const float* wo  = (const float*)d_in[9];
    const float* ln2 = (const float*)d_in[10];
    const float* wg  = (const float*)d_in[11];
    const float* wu  = (const float*)d_in[12];
    const float* wd  = (const float*)d_in[13];
    float* out = (float*)d_out;

    __half *h, *qkv, *attn, *g, *act;
    __half *rwqkv, *rwo, *rwgu, *rwd;
    float *h2, *bqkv;
    float2 *rope;
    cudaGetSymbolAddress((void**)&h,     g_h);
    cudaGetSymbolAddress((void**)&qkv,   g_qkv);
    cudaGetSymbolAddress((void**)&attn,  g_attn);
    cudaGetSymbolAddress((void**)&h2,    g_h2);
    cudaGetSymbolAddress((void**)&g,     g_g);
    cudaGetSymbolAddress((void**)&act,   g_act);
    cudaGetSymbolAddress((void**)&rwqkv, g_wqkv);
    cudaGetSymbolAddress((void**)&rwo,   g_wo);
    cudaGetSymbolAddress((void**)&rwgu,  g_wgu);
    cudaGetSymbolAddress((void**)&rwd,   g_wd);
    cudaGetSymbolAddress((void**)&bqkv,  g_bqkv);
    cudaGetSymbolAddress((void**)&rope,  g_rope);

    cudaFuncSetAttribute((const void*)hgemm_kernel<1,__half>, cudaFuncAttributeMaxDynamicSharedMemorySize, GEMM_SMEM);
    cudaFuncSetAttribute((const void*)hgemm_kernel<2,float>,  cudaFuncAttributeMaxDynamicSharedMemorySize, GEMM_SMEM);
    cudaFuncSetAttribute((const void*)hgemm_kernel<3,__half>, cudaFuncAttributeMaxDynamicSharedMemorySize, GEMM_SMEM);
    cudaFuncSetAttribute((const void*)flash_mma_kernel, cudaFuncAttributeMaxDynamicSharedMemorySize, FA_SMEM);

    // 0. weights -> fp16, rope table, bias concat
    rope_table_kernel<<<(SS*64)/256, 256>>>(rope);
    f2h_kernel<<<(DD*DD/4)/256, 256>>>(wq, rwqkv);
    f2h_kernel<<<(256*DD/4)/256, 256>>>(wk, rwqkv + 2048*DD);
    f2h_kernel<<<(256*DD/4)/256, 256>>>(wv, rwqkv + 2304*DD);
    f2h_kernel<<<(DD*DD/4)/256, 256>>>(wo, rwo);
    f2h_ilv_kernel<<<(II*DD/4)/256, 256>>>(wg, wu, rwgu);
    f2h_kernel<<<(DD*II/4)/256, 256>>>(wd, rwd);
    bias_concat_kernel<<<10, 256>>>(bq, bk, bv, bqkv);

    // 1. h = rmsnorm(x, ln1) -> half
    rmsnorm_kernel<<<MM, 256>>>(x, ln1, h);

    // 2. fused qkv projection (+bias); 128x128 tiles, 2 CTAs/SM
    hgemm_kernel<1,__half><<<dim3(QKVN/128, MM/128), 256, GEMM_SMEM>>>(h, rwqkv, bqkv, qkv, MM, QKVN, DD);

    // 3. RoPE for K only (Q rope fused into attention)
    rope_k_kernel<<<(MM*KVH*64)/256, 256>>>(qkv, rope);

    // 4. attention (paired q-tiles: uniform 34 KV-tiles per CTA)
    flash_mma_kernel<<<dim3(NQT/2, BB*HH), 256, FA_SMEM>>>(qkv, rope, attn);

    // 5. h2 = x + attn @ wo^T (fp32)
    hgemm_kernel<2,float><<<dim3(DD/128, MM/128), 256, GEMM_SMEM>>>(attn, rwo, x, h2, MM, DD, DD);

    // 6. g = rmsnorm(h2, ln2) -> half
    rmsnorm_kernel<<<MM, 256>>>(h2, ln2, g);

    // 7. fused MLP gate/up + silu
    hgemm_kernel<3,__half><<<dim3(2*II/128, MM/128), 256, GEMM_SMEM>>>(g, rwgu, nullptr, act, MM, II, DD);

    // 8. out = h2 + act @ wd^T (fp32)
    hgemm_kernel<2,float><<<dim3(DD/128, MM/128), 256, GEMM_SMEM>>>(act, rwd, h2, out, MM, DD, II);
}

// round 16
// speedup vs baseline: 1.2739x; 1.0873x over previous
#include <cuda_runtime.h>
#include <cuda_fp16.h>
#include <math.h>
#include <stdint.h>

// Problem constants
#define BB 2
#define SS 2048
#define DD 2048
#define HH 16
#define KVH 2
#define HDIM 128
#define II 5504
#define MM (BB*SS)          // 4096
#define QKVN 2560           // 2048 q + 256 k + 256 v

// ---------------- scratch (device globals; allocation-free) ----------------
__device__ __half g_h   [MM*DD];
__device__ __half g_qkv [MM*QKVN];
__device__ __half g_attn[MM*DD];
__device__ float  g_h2  [MM*DD];
__device__ __half g_g   [MM*DD];
__device__ __half g_act [MM*II];          // silu(gate)*up
__device__ __half g_wqkv[QKVN*DD];
__device__ __half g_wo[DD*DD];
__device__ __half g_wgu[2*II*DD];         // interleaved gate/up weights (16-row granules)
__device__ __half g_wd[DD*II];
__device__ float  g_bqkv[QKVN];
__device__ float2 g_rope[SS*64];          // (cos, sin) per (pos, d)

// ---------------- small helpers ----------------
__inline__ __device__ float warpReduceSum(float v) {
    #pragma unroll
    for (int m = 16; m; m >>= 1) v += __shfl_xor_sync(0xffffffffu, v, m);
    return v;
}
__device__ __forceinline__ uint32_t smem_u32(const void* p) {
    uint32_t a;
    asm("{ .reg .u64 t; cvta.to.shared.u64 t, %1; cvt.u32.u64 %0, t; }" : "=r"(a) : "l"(p));
    return a;
}
__device__ __forceinline__ void cp16(uint32_t s, const void* g) {
    asm volatile("cp.async.cg.shared.global [%0], [%1], 16;" :: "r"(s), "l"(g));
}
__device__ __forceinline__ void cp_commit() {
    asm volatile("cp.async.commit_group;" ::: "memory");
}
__device__ __forceinline__ void mma_f16(float* c, const uint32_t* a, const uint32_t* b) {
    asm volatile(
        "mma.sync.aligned.m16n8k16.row.col.f32.f16.f16.f32 "
        "{%0,%1,%2,%3}, {%4,%5,%6,%7}, {%8,%9}, {%0,%1,%2,%3};"
        : "+f"(c[0]), "+f"(c[1]), "+f"(c[2]), "+f"(c[3])
        : "r"(a[0]), "r"(a[1]), "r"(a[2]), "r"(a[3]), "r"(b[0]), "r"(b[1]));
}
__device__ __forceinline__ void ldm_x4(uint32_t* r, uint32_t addr) {
    asm volatile("ldmatrix.sync.aligned.m8n8.x4.shared.b16 {%0,%1,%2,%3}, [%4];"
        : "=r"(r[0]), "=r"(r[1]), "=r"(r[2]), "=r"(r[3]) : "r"(addr));
}
__device__ __forceinline__ float silu_f(float x) {
    return x / (1.f + __expf(-x));
}

// ---------------- FP16 mma.sync GEMM: C = A(MxK) @ B(NxK)^T ----------------
// CTA tile 128x128x64, warp tile 64x32 (8 warps, 2 M x 4 N), 3-stage cp.async,
// ldmatrix.x4, pitch 72 halves. 110.6KB smem -> 2 CTAs/SM.
#define GPITCH_B  144
#define A_TILE_B  (128*GPITCH_B)
#define B_TILE_B  (128*GPITCH_B)
#define STAGE_B   (A_TILE_B + B_TILE_B)
#define GEMM_SMEM (3*STAGE_B)              // 110592

// MODE 0: plain->half, MODE 1: +bias[col]->half, MODE 2: +aux[row*N+col]->float,
// MODE 3: silu-fused MLP (B interleaved gate/up, 16-row granules) -> half
template<int MODE, typename CT>
__global__ __launch_bounds__(256, 2) void hgemm_kernel(
    const __half* __restrict__ A, const __half* __restrict__ Bw,
    const float* __restrict__ aux, CT* __restrict__ C,
    int M, int N, int K)
{
    extern __shared__ __half smh[];
    const uint32_t sb = smem_u32(smh);
    const int tid  = threadIdx.x;
    const int lane = tid & 31;
    const int wid  = tid >> 5;
    const int wm   = wid >> 2;
    const int wn   = wid & 3;
    const int gi   = lane >> 2, tg = lane & 3;
    const int bn = blockIdx.x, bm = blockIdx.y;
    const __half* Ab = A  + (size_t)bm * 128 * K;
    const __half* Bb = Bw + (size_t)bn * 128 * K;

    const int nk = K >> 6;

    const int lrow = tid >> 3, lc = tid & 7;
    auto load_stage = [&](int stage, int kt) {
        const uint32_t as = sb + (uint32_t)stage * STAGE_B;
        const uint32_t bs = as + A_TILE_B;
        const __half* Asrc = Ab + (size_t)kt * 64;
        const __half* Bsrc = Bb + (size_t)kt * 64;
        #pragma unroll
        for (int u = 0; u < 4; u++) {
            int row = lrow + u * 32;
            cp16(as + (uint32_t)(row * GPITCH_B + lc * 16),
                 Asrc + (size_t)row * K + lc * 8);
        }
        #pragma unroll
        for (int u = 0; u < 4; u++) {
            int row = lrow + u * 32;
            cp16(bs + (uint32_t)(row * GPITCH_B + lc * 16),
                 Bsrc + (size_t)row * K + lc * 8);
        }
        cp_commit();
    };

    float acc[4][4][4];
    #pragma unroll
    for (int i = 0; i < 4; i++)
        #pragma unroll
        for (int j = 0; j < 4; j++)
            #pragma unroll
            for (int e = 0; e < 4; e++) acc[i][j][e] = 0.f;

    load_stage(0, 0);
    if (nk > 1) load_stage(1, 1);

    const uint32_t a_off = (uint32_t)((lane & 15) * GPITCH_B + ((lane >> 4) << 4));
    const uint32_t b_off = (uint32_t)(((lane & 7) + ((lane >> 4) << 3)) * GPITCH_B
                                      + (((lane >> 3) & 1) << 4));

    int rd = 0, wr = 2;
    for (int kt = 0; kt < nk; kt++) {
        if (kt + 1 < nk)
            asm volatile("cp.async.wait_group 1;" ::: "memory");
        else
            asm volatile("cp.async.wait_group 0;" ::: "memory");
        __syncthreads();
        if (kt + 2 < nk) load_stage(wr, kt + 2);

        const uint32_t as = sb + (uint32_t)rd * STAGE_B;
        const uint32_t bs = as + A_TILE_B;
        const uint32_t a_base = as + (uint32_t)(wm * 64) * GPITCH_B + a_off;
        const uint32_t b_base = bs + (uint32_t)(wn * 32) * GPITCH_B + b_off;

        #pragma unroll
        for (int kk = 0; kk < 4; kk++) {
            const uint32_t k0b = kk * 32;
            uint32_t a[4][4], b[4][2];
            #pragma unroll
            for (int mt = 0; mt < 4; mt++)
                ldm_x4(a[mt], a_base + (uint32_t)(mt * 16) * GPITCH_B + k0b);
            #pragma unroll
            for (int nb = 0; nb < 2; nb++) {
                uint32_t r[4];
                ldm_x4(r, b_base + (uint32_t)(nb * 16) * GPITCH_B + k0b);
                b[2*nb][0] = r[0]; b[2*nb][1] = r[1];
                b[2*nb+1][0] = r[2]; b[2*nb+1][1] = r[3];
            }
            #pragma unroll
            for (int mt = 0; mt < 4; mt++)
                #pragma unroll
                for (int nt = 0; nt < 4; nt++)
                    mma_f16(acc[mt][nt], a[mt], b[nt]);
        }
        rd = (rd == 2) ? 0 : rd + 1;
        wr = (wr == 2) ? 0 : wr + 1;
    }

    if (MODE == 3) {
        const int j = bn * 4 + wn;
        #pragma unroll
        for (int mt = 0; mt < 4; mt++) {
            const int r0 = bm * 128 + wm * 64 + mt * 16 + gi;
            #pragma unroll
            for (int jt = 0; jt < 2; jt++) {
                const int c = j * 16 + jt * 8 + 2*tg;
                float a00 = silu_f(acc[mt][jt][0]) * acc[mt][jt+2][0];
                float a01 = silu_f(acc[mt][jt][1]) * acc[mt][jt+2][1];
                float a10 = silu_f(acc[mt][jt][2]) * acc[mt][jt+2][2];
                float a11 = silu_f(acc[mt][jt][3]) * acc[mt][jt+2][3];
                *(__half2*)((__half*)C + (size_t)r0 * N + c) = __floats2half2_rn(a00, a01);
                *(__half2*)((__half*)C + (size_t)(r0 + 8) * N + c) = __floats2half2_rn(a10, a11);
            }
        }
        return;
    }
    #pragma unroll
    for (int mt = 0; mt < 4; mt++) {
        const int r0 = bm * 128 + wm * 64 + mt * 16 + gi;
        #pragma unroll
        for (int nt = 0; nt < 4; nt++) {
            const int c = bn * 128 + wn * 32 + nt * 8 + 2*tg;
            float v00 = acc[mt][nt][0], v01 = acc[mt][nt][1];
            float v10 = acc[mt][nt][2], v11 = acc[mt][nt][3];
            if (MODE == 1) {
                float bx = aux[c], by = aux[c + 1];
                v00 += bx; v01 += by; v10 += bx; v11 += by;
            }
            if (MODE == 2) {
                const float2 a0 = *(const float2*)(aux + (size_t)r0 * N + c);
                const float2 a1 = *(const float2*)(aux + (size_t)(r0 + 8) * N + c);
                v00 += a0.x; v01 += a0.y; v10 += a1.x; v11 += a1.y;
                *(float2*)((float*)C + (size_t)r0 * N + c) = make_float2(v00, v01);
                *(float2*)((float*)C + (size_t)(r0 + 8) * N + c) = make_float2(v10, v11);
            } else {
                *(__half2*)((__half*)C + (size_t)r0 * N + c) = __floats2half2_rn(v00, v01);
                *(__half2*)((__half*)C + (size_t)(r0 + 8) * N + c) = __floats2half2_rn(v10, v11);
            }
        }
    }
}

// ---------------- RMSNorm: fp32 in -> half out ----------------
__global__ __launch_bounds__(256) void rmsnorm_kernel(
    const float* __restrict__ x, const float* __restrict__ w, __half* __restrict__ out)
{
    int row = blockIdx.x;
    const float4* xr = (const float4*)(x + (size_t)row * DD);
    const float4* wr = (const float4*)w;
    float4 v0 = xr[threadIdx.x];
    float4 v1 = xr[threadIdx.x + 256];
    float s = v0.x*v0.x + v0.y*v0.y + v0.z*v0.z + v0.w*v0.w
            + v1.x*v1.x + v1.y*v1.y + v1.z*v1.z + v1.w*v1.w;
    s = warpReduceSum(s);
    __shared__ float smw[8];
    __shared__ float sinv;
    if ((threadIdx.x & 31) == 0) smw[threadIdx.x >> 5] = s;
    __syncthreads();
    if (threadIdx.x == 0) {
        float t = 0.f;
        #pragma unroll
        for (int i = 0; i < 8; i++) t += smw[i];
        sinv = rsqrtf(t * (1.0f / DD) + 1e-6f);
    }
    __syncthreads();
    float inv = sinv;
    float4 w0 = wr[threadIdx.x], w1 = wr[threadIdx.x + 256];
    __half2* orow = (__half2*)(out + (size_t)row * DD);
    orow[2*threadIdx.x]       = __floats2half2_rn(v0.x*inv*w0.x, v0.y*inv*w0.y);
    orow[2*threadIdx.x + 1]   = __floats2half2_rn(v0.z*inv*w0.z, v0.w*inv*w0.w);
    orow[512 + 2*threadIdx.x] = __floats2half2_rn(v1.x*inv*w1.x, v1.y*inv*w1.y);
    orow[513 + 2*threadIdx.x] = __floats2half2_rn(v1.z*inv*w1.z, v1.w*inv*w1.w);
}

// ---------------- fp32 -> fp16 conversion ----------------
__global__ __launch_bounds__(256) void f2h_kernel(
    const float* __restrict__ in, __half* __restrict__ out)
{
    size_t i = (size_t)blockIdx.x * 256 + threadIdx.x;
    float4 v = ((const float4*)in)[i];
    ((__half2*)out)[2*i]   = __floats2half2_rn(v.x, v.y);
    ((__half2*)out)[2*i+1] = __floats2half2_rn(v.z, v.w);
}

// ---------------- gate/up weights -> interleaved fp16 (16-row granules) ----------------
__global__ __launch_bounds__(256) void f2h_ilv_kernel(
    const float* __restrict__ wg, const float* __restrict__ wu, __half* __restrict__ out)
{
    size_t i = (size_t)blockIdx.x * 256 + threadIdx.x;
    int c4 = (int)(i % (DD/4));
    int r  = (int)(i / (DD/4));
    int rg = 32*(r >> 4) + (r & 15);
    float4 gv = ((const float4*)wg)[i];
    float4 uv = ((const float4*)wu)[i];
    __half2* og = (__half2*)(out + (size_t)rg * DD + c4*4);
    og[0] = __floats2half2_rn(gv.x, gv.y);
    og[1] = __floats2half2_rn(gv.z, gv.w);
    __half2* ou = (__half2*)(out + (size_t)(rg + 16) * DD + c4*4);
    ou[0] = __floats2half2_rn(uv.x, uv.y);
    ou[1] = __floats2half2_rn(uv.z, uv.w);
}

// ---------------- bias concat (q|k|v) ----------------
__global__ void bias_concat_kernel(
    const float* __restrict__ bq, const float* __restrict__ bk,
    const float* __restrict__ bv, float* __restrict__ o)
{
    int i = blockIdx.x * 256 + threadIdx.x;
    if (i < 2048) o[i] = bq[i];
    else if (i < 2304) o[i] = bk[i - 2048];
    else if (i < QKVN) o[i] = bv[i - 2304];
}

// ---------------- RoPE cos/sin table ----------------
__global__ __launch_bounds__(256) void rope_table_kernel(float2* __restrict__ tab)
{
    int idx = blockIdx.x * 256 + threadIdx.x;   // SS*64
    int pos = idx >> 6, d = idx & 63;
    float inv = exp2f(-(float)d * (13.287712379549449f / 64.0f));
    float fr  = (float)pos * inv;
    float c, sn;
    __sincosf(fr, &sn, &c);
    tab[idx] = make_float2(c, sn);
}

// ---------------- RoPE for K (in place, table-based; one batch: SS rows) ----------------
__global__ __launch_bounds__(256) void rope_k_kernel(
    __half* __restrict__ buf, const float2* __restrict__ tab)
{
    int idx = blockIdx.x * 256 + threadIdx.x;   // SS*KVH*64
    int d   = idx & 63;
    int t   = idx >> 6;
    int hh  = t % KVH;
    int m   = t / KVH;                          // = pos within batch
    float2 cs = tab[m * 64 + d];
    __half* p = buf + (size_t)m * QKVN + 2048 + hh * HDIM + d;
    float x1 = __half2float(p[0]), x2 = __half2float(p[64]);
    p[0]  = __float2half_rn(x1 * cs.x - x2 * cs.y);
    p[64] = __float2half_rn(x2 * cs.x + x1 * cs.y);
}

// ---------------- Flash attention (causal, GQA), fp16 mma, Q-rope fused ----------------
// One batch per launch (base pointers pre-offset). grid = (NQT/2, HH).
// Paired q-tiles: CTA x handles qt = x and qt = NQT-1-x -> uniform 34 tiles/CTA.
#define FQP 136
#define FPP 72
#define NQT (SS/128)
#define FA_SMEM ((128*FQP + 4*64*FQP + 128*FPP) * 2)   // Q + 2-stage K/V + P

__global__ __launch_bounds__(256, 1) void flash_mma_kernel(
    const __half* __restrict__ QKV, const float2* __restrict__ rope,
    __half* __restrict__ O)
{
    extern __shared__ __half smh[];
    __half* Qs  = smh;                       // [128][136]
    __half* Kst = Qs + 128*FQP;              // [2][64][136]
    __half* Vst = Kst + 2*64*FQP;            // [2][64][136]
    __half* Ps  = Vst + 2*64*FQP;            // [128][72]
    const uint32_t sbK = smem_u32(Kst);
    const uint32_t sbV = smem_u32(Vst);

    const int h = blockIdx.y, kvh = h >> 3;
    const int tid = threadIdx.x, lane = tid & 31, wid = tid >> 5;
    const int gi = lane >> 2, tg = lane & 3;
    const float scale = 0.088388347648318447f;
    const int r0 = wid*16 + gi;

    #pragma unroll 1
    for (int pass = 0; pass < 2; pass++) {
        const int qt = pass ? (NQT - 1 - (int)blockIdx.x) : (int)blockIdx.x;
        if (pass) __syncthreads();   // all warps done reading Qs/Ps from pass 0

        // Q tile with fused RoPE
        for (int f = tid; f < 1024; f += 256) {
            int r = f >> 3, c4 = f & 7;
            const __half* qp = QKV + (size_t)(qt*128 + r) * QKVN + h*HDIM + c4*8;
            uint4 lo4 = *(const uint4*)qp;
            uint4 hi4 = *(const uint4*)(qp + 64);
            const float2* tb = rope + (qt*128 + r) * 64 + c4*8;
            __half2* loh = (__half2*)&lo4;
            __half2* hih = (__half2*)&hi4;
            uint4 olo, ohi;
            __half2* oloh = (__half2*)&olo;
            __half2* ohih = (__half2*)&ohi;
            #pragma unroll
            for (int i = 0; i < 4; i++) {
                float2 x1 = __half22float2(loh[i]);
                float2 x2 = __half22float2(hih[i]);
                float2 c0 = tb[2*i], c1 = tb[2*i+1];
                oloh[i] = __floats2half2_rn(x1.x*c0.x - x2.x*c0.y, x1.y*c1.x - x2.y*c1.y);
                ohih[i] = __floats2half2_rn(x2.x*c0.x + x1.x*c0.y, x2.y*c1.x + x1.y*c1.y);
            }
            *(uint4*)(Qs + r*FQP + c4*8)      = olo;
            *(uint4*)(Qs + r*FQP + c4*8 + 64) = ohi;
        }

        auto load_kv = [&](int st, int kt) {
            const uint32_t kb = sbK + (uint32_t)st * (64*FQP*2);
            const uint32_t vb = sbV + (uint32_t)st * (64*FQP*2);
            #pragma unroll
            for (int u = 0; u < 4; u++) {
                int f = tid + u * 256;
                int r = f >> 4, c8 = f & 15;
                size_t base = (size_t)(kt*64 + r) * QKVN + kvh * HDIM;
                cp16(kb + (uint32_t)(r * (FQP*2) + c8 * 16), QKV + base + 2048 + c8*8);
                cp16(vb + (uint32_t)(r * (FQP*2) + c8 * 16), QKV + base + 2304 + c8*8);
            }
            cp_commit();
        };

        float oacc[16][4];
        #pragma unroll
        for (int i = 0; i < 16; i++)
            #pragma unroll
            for (int e = 0; e < 4; e++) oacc[i][e] = 0.f;
        float mrow[2] = {-1e30f, -1e30f}, lrow[2] = {0.f, 0.f};

        const int kmax = 2*qt + 2;
        load_kv(0, 0);

        for (int kt = 0; kt < kmax; kt++) {
            __syncthreads();
            if (kt + 1 < kmax) {
                load_kv((kt + 1) & 1, kt + 1);
                asm volatile("cp.async.wait_group 1;" ::: "memory");
            } else {
                asm volatile("cp.async.wait_group 0;" ::: "memory");
            }
            __syncthreads();

            if (kt*64 > qt*128 + wid*16 + 15) continue;

            const __half* Ks = Kst + (kt & 1) * 64*FQP;
            const __half* Vs = Vst + (kt & 1) * 64*FQP;

            float sa[8][4];
            #pragma unroll
            for (int nt = 0; nt < 8; nt++)
                #pragma unroll
                for (int e = 0; e < 4; e++) sa[nt][e] = 0.f;
            #pragma unroll
            for (int ks = 0; ks < 8; ks++) {
                const int k0 = ks*16 + 2*tg;
                uint32_t a[4];
                a[0] = *(const uint32_t*)(Qs + r0*FQP + k0);
                a[1] = *(const uint32_t*)(Qs + (r0+8)*FQP + k0);
                a[2] = *(const uint32_t*)(Qs + r0*FQP + k0 + 8);
                a[3] = *(const uint32_t*)(Qs + (r0+8)*FQP + k0 + 8);
                #pragma unroll
                for (int nt = 0; nt < 8; nt++) {
                    const int n = nt*8 + gi;
                    uint32_t bb[2];
                    bb[0] = *(const uint32_t*)(Ks + n*FQP + k0);
                    bb[1] = *(const uint32_t*)(Ks + n*FQP + k0 + 8);
                    mma_f16(sa[nt], a, bb);
                }
            }
            #pragma unroll
            for (int nt = 0; nt < 8; nt++)
                #pragma unroll
                for (int e = 0; e < 4; e++) sa[nt][e] *= scale;
            if (kt >= 2*qt) {
                const int qr0 = qt*128 + r0, qr1 = qr0 + 8;
                #pragma unroll
                for (int nt = 0; nt < 8; nt++) {
                    int kc = kt*64 + nt*8 + 2*tg;
                    if (kc     > qr0) sa[nt][0] = -1e30f;
                    if (kc + 1 > qr0) sa[nt][1] = -1e30f;
                    if (kc     > qr1) sa[nt][2] = -1e30f;
                    if (kc + 1 > qr1) sa[nt][3] = -1e30f;
                }
            }

            float mx0 = -1e30f, mx1 = -1e30f;
            #pragma unroll
            for (int nt = 0; nt < 8; nt++) {
                mx0 = fmaxf(mx0, fmaxf(sa[nt][0], sa[nt][1]));
                mx1 = fmaxf(mx1, fmaxf(sa[nt][2], sa[nt][3]));
            }
            mx0 = fmaxf(mx0, __shfl_xor_sync(0xffffffffu, mx0, 1));
            mx0 = fmaxf(mx0, __shfl_xor_sync(0xffffffffu, mx0, 2));
            mx1 = fmaxf(mx1, __shfl_xor_sync(0xffffffffu, mx1, 1));
            mx1 = fmaxf(mx1, __shfl_xor_sync(0xffffffffu, mx1, 2));
            const float mn0 = fmaxf(mrow[0], mx0), mn1 = fmaxf(mrow[1], mx1);
            const float cr0 = __expf(mrow[0] - mn0), cr1 = __expf(mrow[1] - mn1);
            float s0 = 0.f, s1 = 0.f;
            #pragma unroll
            for (int nt = 0; nt < 8; nt++) {
                __half2 p0 = __floats2half2_rn(__expf(sa[nt][0] - mn0), __expf(sa[nt][1] - mn0));
                __half2 p1 = __floats2half2_rn(__expf(sa[nt][2] - mn1), __expf(sa[nt][3] - mn1));
                float2 p0f = __half22float2(p0), p1f = __half22float2(p1);
                s0 += p0f.x + p0f.y;
                s1 += p1f.x + p1f.y;
                *(__half2*)(Ps + r0*FPP + nt*8 + 2*tg)     = p0;
                *(__half2*)(Ps + (r0+8)*FPP + nt*8 + 2*tg) = p1;
            }
            s0 += __shfl_xor_sync(0xffffffffu, s0, 1);
            s0 += __shfl_xor_sync(0xffffffffu, s0, 2);
            s1 += __shfl_xor_sync(0xffffffffu, s1, 1);
            s1 += __shfl_xor_sync(0xffffffffu, s1, 2);
            lrow[0] = lrow[0]*cr0 + s0;
            lrow[1] = lrow[1]*cr1 + s1;
            mrow[0] = mn0; mrow[1] = mn1;
            #pragma unroll
            for (int nt = 0; nt < 16; nt++) {
                oacc[nt][0] *= cr0; oacc[nt][1] *= cr0;
                oacc[nt][2] *= cr1; oacc[nt][3] *= cr1;
            }
            __syncwarp();

            #pragma unroll
            for (int ks = 0; ks < 4; ks++) {
                const int k0 = ks*16 + 2*tg;
                uint32_t a[4];
                a[0] = *(const uint32_t*)(Ps + r0*FPP + k0);
                a[1] = *(const uint32_t*)(Ps + (r0+8)*FPP + k0);
                a[2] = *(const uint32_t*)(Ps + r0*FPP + k0 + 8);
                a[3] = *(const uint32_t*)(Ps + (r0+8)*FPP + k0 + 8);
                #pragma unroll
                for (int ntp = 0; ntp < 8; ntp++) {
                    int kvrow = ks*16 + (lane & 15);
                    int dcol  = (ntp*2 + (lane >> 4)) * 8;
                    uint32_t addr = smem_u32(Vs + kvrow*FQP + dcol);
                    uint32_t b0, b1, b2, b3;
                    asm volatile(
                        "ldmatrix.sync.aligned.m8n8.x4.trans.shared.b16 {%0,%1,%2,%3}, [%4];"
                        : "=r"(b0), "=r"(b1), "=r"(b2), "=r"(b3) : "r"(addr));
                    uint32_t bb0[2] = {b0, b1}, bb1[2] = {b2, b3};
                    mma_f16(oacc[2*ntp],     a, bb0);
                    mma_f16(oacc[2*ntp + 1], a, bb1);
                }
            }
        }

        const float inv0 = 1.0f / lrow[0], inv1 = 1.0f / lrow[1];
        __half* op0 = O + (size_t)(qt*128 + r0)     * DD + h*HDIM + 2*tg;
        __half* op1 = O + (size_t)(qt*128 + r0 + 8) * DD + h*HDIM + 2*tg;
        #pragma unroll
        for (int nt = 0; nt < 16; nt++) {
            *(__half2*)(op0 + nt*8) = __floats2half2_rn(oacc[nt][0]*inv0, oacc[nt][1]*inv0);
            *(__half2*)(op1 + nt*8) = __floats2half2_rn(oacc[nt][2]*inv1, oacc[nt][3]*inv1);
        }
    }
}

// ---------------- launch ----------------
extern "C" void kernel_launch(void* const* d_in, const int* in_sizes, int n_in,
                              void* d_out, int out_size)
{
    (void)in_sizes; (void)n_in; (void)out_size;
    const float* x   = (const float*)d_in[0];
    const float* ln1 = (const float*)d_in[2];
    const float* wq  = (const float*)d_in[3];
    const float* bq  = (const float*)d_in[4];
    const float* wk  = (const float*)d_in[5];
    const float* bk  = (const float*)d_in[6];
    const float* wv  = (const float*)d_in[7];
    const float* bv  = (const float*)d_in[8];
    const float* wo  = (const float*)d_in[9];
    const float* ln2 = (const float*)d_in[10];
    const float* wg  = (const float*)d_in[11];
    const float* wu  = (const float*)d_in[12];
    const float* wd  = (const float*)d_in[13];
    float* out = (float*)d_out;

    __half *h, *qkv, *attn, *g, *act;
    __half *rwqkv, *rwo, *rwgu, *rwd;
    float *h2, *bqkv;
    float2 *rope;
    cudaGetSymbolAddress((void**)&h,     g_h);
    cudaGetSymbolAddress((void**)&qkv,   g_qkv);
    cudaGetSymbolAddress((void**)&attn,  g_attn);
    cudaGetSymbolAddress((void**)&h2,    g_h2);
    cudaGetSymbolAddress((void**)&g,     g_g);
    cudaGetSymbolAddress((void**)&act,   g_act);
    cudaGetSymbolAddress((void**)&rwqkv, g_wqkv);
    cudaGetSymbolAddress((void**)&rwo,   g_wo);
    cudaGetSymbolAddress((void**)&rwgu,  g_wgu);
    cudaGetSymbolAddress((void**)&rwd,   g_wd);
    cudaGetSymbolAddress((void**)&bqkv,  g_bqkv);
    cudaGetSymbolAddress((void**)&rope,  g_rope);

    cudaFuncSetAttribute((const void*)hgemm_kernel<1,__half>, cudaFuncAttributeMaxDynamicSharedMemorySize, GEMM_SMEM);
    cudaFuncSetAttribute((const void*)hgemm_kernel<2,float>,  cudaFuncAttributeMaxDynamicSharedMemorySize, GEMM_SMEM);
    cudaFuncSetAttribute((const void*)hgemm_kernel<3,__half>, cudaFuncAttributeMaxDynamicSharedMemorySize, GEMM_SMEM);
    cudaFuncSetAttribute((const void*)flash_mma_kernel, cudaFuncAttributeMaxDynamicSharedMemorySize, FA_SMEM);

    // Side stream + events for batch-parallel execution
    static cudaStream_t s2 = nullptr;
    static cudaEvent_t eFork = nullptr, eJoin = nullptr;
    if (s2 == nullptr) {
        cudaStreamCreateWithFlags(&s2, cudaStreamNonBlocking);
        cudaEventCreateWithFlags(&eFork, cudaEventDisableTiming);
        cudaEventCreateWithFlags(&eJoin, cudaEventDisableTiming);
    }

    // ---- shared prepass (stream 0) ----
    rope_table_kernel<<<(SS*64)/256, 256>>>(rope);
    f2h_kernel<<<(DD*DD/4)/256, 256>>>(wq, rwqkv);
    f2h_kernel<<<(256*DD/4)/256, 256>>>(wk, rwqkv + 2048*DD);
    f2h_kernel<<<(256*DD/4)/256, 256>>>(wv, rwqkv + 2304*DD);
    f2h_kernel<<<(DD*DD/4)/256, 256>>>(wo, rwo);
    f2h_ilv_kernel<<<(II*DD/4)/256, 256>>>(wg, wu, rwgu);
    f2h_kernel<<<(DD*II/4)/256, 256>>>(wd, rwd);
    bias_concat_kernel<<<10, 256>>>(bq, bk, bv, bqkv);

    cudaEventRecord(eFork, 0);
    cudaStreamWaitEvent(s2, eFork, 0);

    // ---- per-batch chains: batch 0 on stream 0, batch 1 on s2 ----
    for (int b = 0; b < BB; b++) {
        cudaStream_t st = (b == 0) ? (cudaStream_t)0 : s2;
        const size_t m0 = (size_t)b * SS;

        // 1. h = rmsnorm(x, ln1)
        rmsnorm_kernel<<<SS, 256, 0, st>>>(x + m0*DD, ln1, h + m0*DD);

        // 2. fused qkv projection (+bias)
        hgemm_kernel<1,__half><<<dim3(QKVN/128, SS/128), 256, GEMM_SMEM, st>>>(
            h + m0*DD, rwqkv, bqkv, qkv + m0*QKVN, SS, QKVN, DD);

        // 3. K-rope (Q rope fused into attention)
        rope_k_kernel<<<(SS*KVH*64)/256, 256, 0, st>>>(qkv + m0*QKVN, rope);

        // 4. attention (paired q-tiles, per batch)
        flash_mma_kernel<<<dim3(NQT/2, HH), 256, FA_SMEM, st>>>(
            qkv + m0*QKVN, rope, attn + m0*DD);

        // 5. h2 = x + attn @ wo^T (fp32)
        hgemm_kernel<2,float><<<dim3(DD/128, SS/128), 256, GEMM_SMEM, st>>>(
            attn + m0*DD, rwo, x + m0*DD, h2 + m0*DD, SS, DD, DD);

        // 6. g = rmsnorm(h2, ln2)
        rmsnorm_kernel<<<SS, 256, 0, st>>>(h2 + m0*DD, ln2, g + m0*DD);

        // 7. fused MLP gate/up + silu
        hgemm_kernel<3,__half><<<dim3(2*II/128, SS/128), 256, GEMM_SMEM, st>>>(
            g + m0*DD, rwgu, nullptr, act + m0*II, SS, II, DD);

        // 8. out = h2 + act @ wd^T (fp32)
        hgemm_kernel<2,float><<<dim3(DD/128, SS/128), 256, GEMM_SMEM, st>>>(
            act + m0*II, rwd, h2 + m0*DD, out + m0*DD, SS, DD, II);
    }

    // join: stream 0 waits for batch 1
    cudaEventRecord(eJoin, s2);
    cudaStreamWaitEvent(0, eJoin, 0);
}

// round 17
// speedup vs baseline: 1.2802x; 1.0049x over previous
#include <cuda_runtime.h>
#include <cuda_fp16.h>
#include <math.h>
#include <stdint.h>

// Problem constants
#define BB 2
#define SS 2048
#define DD 2048
#define HH 16
#define KVH 2
#define HDIM 128
#define II 5504
#define MM (BB*SS)          // 4096
#define QKVN 2560           // 2048 q + 256 k + 256 v

// ---------------- scratch (device globals; allocation-free) ----------------
__device__ __half g_h   [MM*DD];
__device__ __half g_qkv [MM*QKVN];
__device__ __half g_attn[MM*DD];
__device__ float  g_h2  [MM*DD];
__device__ __half g_g   [MM*DD];
__device__ __half g_act [MM*II];          // silu(gate)*up
__device__ __half g_wqkv[QKVN*DD];
__device__ __half g_wo[DD*DD];
__device__ __half g_wgu[2*II*DD];         // interleaved gate/up weights (16-row granules)
__device__ __half g_wd[DD*II];
__device__ float  g_bqkv[QKVN];
__device__ float2 g_rope[SS*64];          // (cos, sin) per (pos, d)

// ---------------- small helpers ----------------
__inline__ __device__ float warpReduceSum(float v) {
    #pragma unroll
    for (int m = 16; m; m >>= 1) v += __shfl_xor_sync(0xffffffffu, v, m);
    return v;
}
__device__ __forceinline__ uint32_t smem_u32(const void* p) {
    uint32_t a;
    asm("{ .reg .u64 t; cvta.to.shared.u64 t, %1; cvt.u32.u64 %0, t; }" : "=r"(a) : "l"(p));
    return a;
}
__device__ __forceinline__ void cp16(uint32_t s, const void* g) {
    asm volatile("cp.async.cg.shared.global [%0], [%1], 16;" :: "r"(s), "l"(g));
}
__device__ __forceinline__ void cp_commit() {
    asm volatile("cp.async.commit_group;" ::: "memory");
}
__device__ __forceinline__ void mma_f16(float* c, const uint32_t* a, const uint32_t* b) {
    asm volatile(
        "mma.sync.aligned.m16n8k16.row.col.f32.f16.f16.f32 "
        "{%0,%1,%2,%3}, {%4,%5,%6,%7}, {%8,%9}, {%0,%1,%2,%3};"
        : "+f"(c[0]), "+f"(c[1]), "+f"(c[2]), "+f"(c[3])
        : "r"(a[0]), "r"(a[1]), "r"(a[2]), "r"(a[3]), "r"(b[0]), "r"(b[1]));
}
__device__ __forceinline__ void ldm_x4(uint32_t* r, uint32_t addr) {
    asm volatile("ldmatrix.sync.aligned.m8n8.x4.shared.b16 {%0,%1,%2,%3}, [%4];"
        : "=r"(r[0]), "=r"(r[1]), "=r"(r[2]), "=r"(r[3]) : "r"(addr));
}
__device__ __forceinline__ float silu_f(float x) {
    return x / (1.f + __expf(-x));
}

// ---------------- FP16 mma.sync GEMM: C = A(MxK) @ B(NxK)^T ----------------
// CTA tile 128x128x64, warp tile 64x32 (8 warps, 2 M x 4 N), 3-stage cp.async,
// ldmatrix.x4, pitch 72 halves. 110.6KB smem -> 2 CTAs/SM.
#define GPITCH_B  144
#define A_TILE_B  (128*GPITCH_B)
#define B_TILE_B  (128*GPITCH_B)
#define STAGE_B   (A_TILE_B + B_TILE_B)
#define GEMM_SMEM (3*STAGE_B)              // 110592

// MODE 0: plain->half, MODE 1: +bias[col]->half, MODE 2: +aux[row*N+col]->float,
// MODE 3: silu-fused MLP (B interleaved gate/up, 16-row granules) -> half
template<int MODE, typename CT>
__global__ __launch_bounds__(256, 2) void hgemm_kernel(
    const __half* __restrict__ A, const __half* __restrict__ Bw,
    const float* __restrict__ aux, CT* __restrict__ C,
    int M, int N, int K)
{
    extern __shared__ __half smh[];
    const uint32_t sb = smem_u32(smh);
    const int tid  = threadIdx.x;
    const int lane = tid & 31;
    const int wid  = tid >> 5;
    const int wm   = wid >> 2;
    const int wn   = wid & 3;
    const int gi   = lane >> 2, tg = lane & 3;
    const int bn = blockIdx.x, bm = blockIdx.y;
    const __half* Ab = A  + (size_t)bm * 128 * K;
    const __half* Bb = Bw + (size_t)bn * 128 * K;

    const int nk = K >> 6;

    const int lrow = tid >> 3, lc = tid & 7;
    auto load_stage = [&](int stage, int kt) {
        const uint32_t as = sb + (uint32_t)stage * STAGE_B;
        const uint32_t bs = as + A_TILE_B;
        const __half* Asrc = Ab + (size_t)kt * 64;
        const __half* Bsrc = Bb + (size_t)kt * 64;
        #pragma unroll
        for (int u = 0; u < 4; u++) {
            int row = lrow + u * 32;
            cp16(as + (uint32_t)(row * GPITCH_B + lc * 16),
                 Asrc + (size_t)row * K + lc * 8);
        }
        #pragma unroll
        for (int u = 0; u < 4; u++) {
            int row = lrow + u * 32;
            cp16(bs + (uint32_t)(row * GPITCH_B + lc * 16),
                 Bsrc + (size_t)row * K + lc * 8);
        }
        cp_commit();
    };

    float acc[4][4][4];
    #pragma unroll
    for (int i = 0; i < 4; i++)
        #pragma unroll
        for (int j = 0; j < 4; j++)
            #pragma unroll
            for (int e = 0; e < 4; e++) acc[i][j][e] = 0.f;

    load_stage(0, 0);
    if (nk > 1) load_stage(1, 1);

    const uint32_t a_off = (uint32_t)((lane & 15) * GPITCH_B + ((lane >> 4) << 4));
    const uint32_t b_off = (uint32_t)(((lane & 7) + ((lane >> 4) << 3)) * GPITCH_B
                                      + (((lane >> 3) & 1) << 4));

    int rd = 0, wr = 2;
    for (int kt = 0; kt < nk; kt++) {
        if (kt + 1 < nk)
            asm volatile("cp.async.wait_group 1;" ::: "memory");
        else
            asm volatile("cp.async.wait_group 0;" ::: "memory");
        __syncthreads();
        if (kt + 2 < nk) load_stage(wr, kt + 2);

        const uint32_t as = sb + (uint32_t)rd * STAGE_B;
        const uint32_t bs = as + A_TILE_B;
        const uint32_t a_base = as + (uint32_t)(wm * 64) * GPITCH_B + a_off;
        const uint32_t b_base = bs + (uint32_t)(wn * 32) * GPITCH_B + b_off;

        #pragma unroll
        for (int kk = 0; kk < 4; kk++) {
            const uint32_t k0b = kk * 32;
            uint32_t a[4][4], b[4][2];
            #pragma unroll
            for (int mt = 0; mt < 4; mt++)
                ldm_x4(a[mt], a_base + (uint32_t)(mt * 16) * GPITCH_B + k0b);
            #pragma unroll
            for (int nb = 0; nb < 2; nb++) {
                uint32_t r[4];
                ldm_x4(r, b_base + (uint32_t)(nb * 16) * GPITCH_B + k0b);
                b[2*nb][0] = r[0]; b[2*nb][1] = r[1];
                b[2*nb+1][0] = r[2]; b[2*nb+1][1] = r[3];
            }
            #pragma unroll
            for (int mt = 0; mt < 4; mt++)
                #pragma unroll
                for (int nt = 0; nt < 4; nt++)
                    mma_f16(acc[mt][nt], a[mt], b[nt]);
        }
        rd = (rd == 2) ? 0 : rd + 1;
        wr = (wr == 2) ? 0 : wr + 1;
    }

    if (MODE == 3) {
        const int j = bn * 4 + wn;
        #pragma unroll
        for (int mt = 0; mt < 4; mt++) {
            const int r0 = bm * 128 + wm * 64 + mt * 16 + gi;
            #pragma unroll
            for (int jt = 0; jt < 2; jt++) {
                const int c = j * 16 + jt * 8 + 2*tg;
                float a00 = silu_f(acc[mt][jt][0]) * acc[mt][jt+2][0];
                float a01 = silu_f(acc[mt][jt][1]) * acc[mt][jt+2][1];
                float a10 = silu_f(acc[mt][jt][2]) * acc[mt][jt+2][2];
                float a11 = silu_f(acc[mt][jt][3]) * acc[mt][jt+2][3];
                *(__half2*)((__half*)C + (size_t)r0 * N + c) = __floats2half2_rn(a00, a01);
                *(__half2*)((__half*)C + (size_t)(r0 + 8) * N + c) = __floats2half2_rn(a10, a11);
            }
        }
        return;
    }
    #pragma unroll
    for (int mt = 0; mt < 4; mt++) {
        const int r0 = bm * 128 + wm * 64 + mt * 16 + gi;
        #pragma unroll
        for (int nt = 0; nt < 4; nt++) {
            const int c = bn * 128 + wn * 32 + nt * 8 + 2*tg;
            float v00 = acc[mt][nt][0], v01 = acc[mt][nt][1];
            float v10 = acc[mt][nt][2], v11 = acc[mt][nt][3];
            if (MODE == 1) {
                float bx = aux[c], by = aux[c + 1];
                v00 += bx; v01 += by; v10 += bx; v11 += by;
            }
            if (MODE == 2) {
                const float2 a0 = *(const float2*)(aux + (size_t)r0 * N + c);
                const float2 a1 = *(const float2*)(aux + (size_t)(r0 + 8) * N + c);
                v00 += a0.x; v01 += a0.y; v10 += a1.x; v11 += a1.y;
                *(float2*)((float*)C + (size_t)r0 * N + c) = make_float2(v00, v01);
                *(float2*)((float*)C + (size_t)(r0 + 8) * N + c) = make_float2(v10, v11);
            } else {
                *(__half2*)((__half*)C + (size_t)r0 * N + c) = __floats2half2_rn(v00, v01);
                *(__half2*)((__half*)C + (size_t)(r0 + 8) * N + c) = __floats2half2_rn(v10, v11);
            }
        }
    }
}

// ---------------- RMSNorm: fp32 in -> half out ----------------
__global__ __launch_bounds__(256) void rmsnorm_kernel(
    const float* __restrict__ x, const float* __restrict__ w, __half* __restrict__ out)
{
    int row = blockIdx.x;
    const float4* xr = (const float4*)(x + (size_t)row * DD);
    const float4* wr = (const float4*)w;
    float4 v0 = xr[threadIdx.x];
    float4 v1 = xr[threadIdx.x + 256];
    float s = v0.x*v0.x + v0.y*v0.y + v0.z*v0.z + v0.w*v0.w
            + v1.x*v1.x + v1.y*v1.y + v1.z*v1.z + v1.w*v1.w;
    s = warpReduceSum(s);
    __shared__ float smw[8];
    __shared__ float sinv;
    if ((threadIdx.x & 31) == 0) smw[threadIdx.x >> 5] = s;
    __syncthreads();
    if (threadIdx.x == 0) {
        float t = 0.f;
        #pragma unroll
        for (int i = 0; i < 8; i++) t += smw[i];
        sinv = rsqrtf(t * (1.0f / DD) + 1e-6f);
    }
    __syncthreads();
    float inv = sinv;
    float4 w0 = wr[threadIdx.x], w1 = wr[threadIdx.x + 256];
    __half2* orow = (__half2*)(out + (size_t)row * DD);
    orow[2*threadIdx.x]       = __floats2half2_rn(v0.x*inv*w0.x, v0.y*inv*w0.y);
    orow[2*threadIdx.x + 1]   = __floats2half2_rn(v0.z*inv*w0.z, v0.w*inv*w0.w);
    orow[512 + 2*threadIdx.x] = __floats2half2_rn(v1.x*inv*w1.x, v1.y*inv*w1.y);
    orow[513 + 2*threadIdx.x] = __floats2half2_rn(v1.z*inv*w1.z, v1.w*inv*w1.w);
}

// ---------------- fp32 -> fp16 conversion ----------------
__global__ __launch_bounds__(256) void f2h_kernel(
    const float* __restrict__ in, __half* __restrict__ out)
{
    size_t i = (size_t)blockIdx.x * 256 + threadIdx.x;
    float4 v = ((const float4*)in)[i];
    ((__half2*)out)[2*i]   = __floats2half2_rn(v.x, v.y);
    ((__half2*)out)[2*i+1] = __floats2half2_rn(v.z, v.w);
}

// ---------------- gate/up weights -> interleaved fp16 (16-row granules) ----------------
__global__ __launch_bounds__(256) void f2h_ilv_kernel(
    const float* __restrict__ wg, const float* __restrict__ wu, __half* __restrict__ out)
{
    size_t i = (size_t)blockIdx.x * 256 + threadIdx.x;
    int c4 = (int)(i % (DD/4));
    int r  = (int)(i / (DD/4));
    int rg = 32*(r >> 4) + (r & 15);
    float4 gv = ((const float4*)wg)[i];
    float4 uv = ((const float4*)wu)[i];
    __half2* og = (__half2*)(out + (size_t)rg * DD + c4*4);
    og[0] = __floats2half2_rn(gv.x, gv.y);
    og[1] = __floats2half2_rn(gv.z, gv.w);
    __half2* ou = (__half2*)(out + (size_t)(rg + 16) * DD + c4*4);
    ou[0] = __floats2half2_rn(uv.x, uv.y);
    ou[1] = __floats2half2_rn(uv.z, uv.w);
}

// ---------------- bias concat (q|k|v) ----------------
__global__ void bias_concat_kernel(
    const float* __restrict__ bq, const float* __restrict__ bk,
    const float* __restrict__ bv, float* __restrict__ o)
{
    int i = blockIdx.x * 256 + threadIdx.x;
    if (i < 2048) o[i] = bq[i];
    else if (i < 2304) o[i] = bk[i - 2048];
    else if (i < QKVN) o[i] = bv[i - 2304];
}

// ---------------- RoPE cos/sin table ----------------
__global__ __launch_bounds__(256) void rope_table_kernel(float2* __restrict__ tab)
{
    int idx = blockIdx.x * 256 + threadIdx.x;   // SS*64
    int pos = idx >> 6, d = idx & 63;
    float inv = exp2f(-(float)d * (13.287712379549449f / 64.0f));
    float fr  = (float)pos * inv;
    float c, sn;
    __sincosf(fr, &sn, &c);
    tab[idx] = make_float2(c, sn);
}

// ---------------- RoPE for K (in place, table-based; one batch: SS rows) ----------------
__global__ __launch_bounds__(256) void rope_k_kernel(
    __half* __restrict__ buf, const float2* __restrict__ tab)
{
    int idx = blockIdx.x * 256 + threadIdx.x;   // SS*KVH*64
    int d   = idx & 63;
    int t   = idx >> 6;
    int hh  = t % KVH;
    int m   = t / KVH;
    float2 cs = tab[m * 64 + d];
    __half* p = buf + (size_t)m * QKVN + 2048 + hh * HDIM + d;
    float x1 = __half2float(p[0]), x2 = __half2float(p[64]);
    p[0]  = __float2half_rn(x1 * cs.x - x2 * cs.y);
    p[64] = __float2half_rn(x2 * cs.x + x1 * cs.y);
}

// ---------------- Flash attention (causal, GQA), fp16 mma, Q-rope fused ----------------
// One batch per launch (base pointers pre-offset). grid = (NQT/2, HH).
// Paired q-tiles: CTA x handles qt = x and qt = NQT-1-x -> uniform 34 tiles/CTA.
#define FQP 136
#define FPP 72
#define NQT (SS/128)
#define FA_SMEM ((128*FQP + 4*64*FQP + 128*FPP) * 2)   // Q + 2-stage K/V + P

__global__ __launch_bounds__(256, 1) void flash_mma_kernel(
    const __half* __restrict__ QKV, const float2* __restrict__ rope,
    __half* __restrict__ O)
{
    extern __shared__ __half smh[];
    __half* Qs  = smh;                       // [128][136]
    __half* Kst = Qs + 128*FQP;              // [2][64][136]
    __half* Vst = Kst + 2*64*FQP;            // [2][64][136]
    __half* Ps  = Vst + 2*64*FQP;            // [128][72]
    const uint32_t sbK = smem_u32(Kst);
    const uint32_t sbV = smem_u32(Vst);

    const int h = blockIdx.y, kvh = h >> 3;
    const int tid = threadIdx.x, lane = tid & 31, wid = tid >> 5;
    const int gi = lane >> 2, tg = lane & 3;
    const float scale = 0.088388347648318447f;
    const int r0 = wid*16 + gi;

    #pragma unroll 1
    for (int pass = 0; pass < 2; pass++) {
        const int qt = pass ? (NQT - 1 - (int)blockIdx.x) : (int)blockIdx.x;
        if (pass) __syncthreads();

        // Q tile with fused RoPE
        for (int f = tid; f < 1024; f += 256) {
            int r = f >> 3, c4 = f & 7;
            const __half* qp = QKV + (size_t)(qt*128 + r) * QKVN + h*HDIM + c4*8;
            uint4 lo4 = *(const uint4*)qp;
            uint4 hi4 = *(const uint4*)(qp + 64);
            const float2* tb = rope + (qt*128 + r) * 64 + c4*8;
            __half2* loh = (__half2*)&lo4;
            __half2* hih = (__half2*)&hi4;
            uint4 olo, ohi;
            __half2* oloh = (__half2*)&olo;
            __half2* ohih = (__half2*)&ohi;
            #pragma unroll
            for (int i = 0; i < 4; i++) {
                float2 x1 = __half22float2(loh[i]);
                float2 x2 = __half22float2(hih[i]);
                float2 c0 = tb[2*i], c1 = tb[2*i+1];
                oloh[i] = __floats2half2_rn(x1.x*c0.x - x2.x*c0.y, x1.y*c1.x - x2.y*c1.y);
                ohih[i] = __floats2half2_rn(x2.x*c0.x + x1.x*c0.y, x2.y*c1.x + x1.y*c1.y);
            }
            *(uint4*)(Qs + r*FQP + c4*8)      = olo;
            *(uint4*)(Qs + r*FQP + c4*8 + 64) = ohi;
        }

        auto load_kv = [&](int st, int kt) {
            const uint32_t kb = sbK + (uint32_t)st * (64*FQP*2);
            const uint32_t vb = sbV + (uint32_t)st * (64*FQP*2);
            #pragma unroll
            for (int u = 0; u < 4; u++) {
                int f = tid + u * 256;
                int r = f >> 4, c8 = f & 15;
                size_t base = (size_t)(kt*64 + r) * QKVN + kvh * HDIM;
                cp16(kb + (uint32_t)(r * (FQP*2) + c8 * 16), QKV + base + 2048 + c8*8);
                cp16(vb + (uint32_t)(r * (FQP*2) + c8 * 16), QKV + base + 2304 + c8*8);
            }
            cp_commit();
        };

        float oacc[16][4];
        #pragma unroll
        for (int i = 0; i < 16; i++)
            #pragma unroll
            for (int e = 0; e < 4; e++) oacc[i][e] = 0.f;
        float mrow[2] = {-1e30f, -1e30f}, lrow[2] = {0.f, 0.f};

        const int kmax = 2*qt + 2;
        load_kv(0, 0);

        for (int kt = 0; kt < kmax; kt++) {
            __syncthreads();
            if (kt + 1 < kmax) {
                load_kv((kt + 1) & 1, kt + 1);
                asm volatile("cp.async.wait_group 1;" ::: "memory");
            } else {
                asm volatile("cp.async.wait_group 0;" ::: "memory");
            }
            __syncthreads();

            if (kt*64 > qt*128 + wid*16 + 15) continue;

            const __half* Ks = Kst + (kt & 1) * 64*FQP;
            const __half* Vs = Vst + (kt & 1) * 64*FQP;

            float sa[8][4];
            #pragma unroll
            for (int nt = 0; nt < 8; nt++)
                #pragma unroll
                for (int e = 0; e < 4; e++) sa[nt][e] = 0.f;
            #pragma unroll
            for (int ks = 0; ks < 8; ks++) {
                const int k0 = ks*16 + 2*tg;
                uint32_t a[4];
                a[0] = *(const uint32_t*)(Qs + r0*FQP + k0);
                a[1] = *(const uint32_t*)(Qs + (r0+8)*FQP + k0);
                a[2] = *(const uint32_t*)(Qs + r0*FQP + k0 + 8);
                a[3] = *(const uint32_t*)(Qs + (r0+8)*FQP + k0 + 8);
                #pragma unroll
                for (int nt = 0; nt < 8; nt++) {
                    const int n = nt*8 + gi;
                    uint32_t bb[2];
                    bb[0] = *(const uint32_t*)(Ks + n*FQP + k0);
                    bb[1] = *(const uint32_t*)(Ks + n*FQP + k0 + 8);
                    mma_f16(sa[nt], a, bb);
                }
            }
            #pragma unroll
            for (int nt = 0; nt < 8; nt++)
                #pragma unroll
                for (int e = 0; e < 4; e++) sa[nt][e] *= scale;
            if (kt >= 2*qt) {
                const int qr0 = qt*128 + r0, qr1 = qr0 + 8;
                #pragma unroll
                for (int nt = 0; nt < 8; nt++) {
                    int kc = kt*64 + nt*8 + 2*tg;
                    if (kc     > qr0) sa[nt][0] = -1e30f;
                    if (kc + 1 > qr0) sa[nt][1] = -1e30f;
                    if (kc     > qr1) sa[nt][2] = -1e30f;
                    if (kc + 1 > qr1) sa[nt][3] = -1e30f;
                }
            }

            float mx0 = -1e30f, mx1 = -1e30f;
            #pragma unroll
            for (int nt = 0; nt < 8; nt++) {
                mx0 = fmaxf(mx0, fmaxf(sa[nt][0], sa[nt][1]));
                mx1 = fmaxf(mx1, fmaxf(sa[nt][2], sa[nt][3]));
            }
            mx0 = fmaxf(mx0, __shfl_xor_sync(0xffffffffu, mx0, 1));
            mx0 = fmaxf(mx0, __shfl_xor_sync(0xffffffffu, mx0, 2));
            mx1 = fmaxf(mx1, __shfl_xor_sync(0xffffffffu, mx1, 1));
            mx1 = fmaxf(mx1, __shfl_xor_sync(0xffffffffu, mx1, 2));
            const float mn0 = fmaxf(mrow[0], mx0), mn1 = fmaxf(mrow[1], mx1);
            const float cr0 = __expf(mrow[0] - mn0), cr1 = __expf(mrow[1] - mn1);
            float s0 = 0.f, s1 = 0.f;
            #pragma unroll
            for (int nt = 0; nt < 8; nt++) {
                __half2 p0 = __floats2half2_rn(__expf(sa[nt][0] - mn0), __expf(sa[nt][1] - mn0));
                __half2 p1 = __floats2half2_rn(__expf(sa[nt][2] - mn1), __expf(sa[nt][3] - mn1));
                float2 p0f = __half22float2(p0), p1f = __half22float2(p1);
                s0 += p0f.x + p0f.y;
                s1 += p1f.x + p1f.y;
                *(__half2*)(Ps + r0*FPP + nt*8 + 2*tg)     = p0;
                *(__half2*)(Ps + (r0+8)*FPP + nt*8 + 2*tg) = p1;
            }
            s0 += __shfl_xor_sync(0xffffffffu, s0, 1);
            s0 += __shfl_xor_sync(0xffffffffu, s0, 2);
            s1 += __shfl_xor_sync(0xffffffffu, s1, 1);
            s1 += __shfl_xor_sync(0xffffffffu, s1, 2);
            lrow[0] = lrow[0]*cr0 + s0;
            lrow[1] = lrow[1]*cr1 + s1;
            mrow[0] = mn0; mrow[1] = mn1;
            #pragma unroll
            for (int nt = 0; nt < 16; nt++) {
                oacc[nt][0] *= cr0; oacc[nt][1] *= cr0;
                oacc[nt][2] *= cr1; oacc[nt][3] *= cr1;
            }
            __syncwarp();

            #pragma unroll
            for (int ks = 0; ks < 4; ks++) {
                const int k0 = ks*16 + 2*tg;
                uint32_t a[4];
                a[0] = *(const uint32_t*)(Ps + r0*FPP + k0);
                a[1] = *(const uint32_t*)(Ps + (r0+8)*FPP + k0);
                a[2] = *(const uint32_t*)(Ps + r0*FPP + k0 + 8);
                a[3] = *(const uint32_t*)(Ps + (r0+8)*FPP + k0 + 8);
                #pragma unroll
                for (int ntp = 0; ntp < 8; ntp++) {
                    int kvrow = ks*16 + (lane & 15);
                    int dcol  = (ntp*2 + (lane >> 4)) * 8;
                    uint32_t addr = smem_u32(Vs + kvrow*FQP + dcol);
                    uint32_t b0, b1, b2, b3;
                    asm volatile(
                        "ldmatrix.sync.aligned.m8n8.x4.trans.shared.b16 {%0,%1,%2,%3}, [%4];"
                        : "=r"(b0), "=r"(b1), "=r"(b2), "=r"(b3) : "r"(addr));
                    uint32_t bb0[2] = {b0, b1}, bb1[2] = {b2, b3};
                    mma_f16(oacc[2*ntp],     a, bb0);
                    mma_f16(oacc[2*ntp + 1], a, bb1);
                }
            }
        }

        const float inv0 = 1.0f / lrow[0], inv1 = 1.0f / lrow[1];
        __half* op0 = O + (size_t)(qt*128 + r0)     * DD + h*HDIM + 2*tg;
        __half* op1 = O + (size_t)(qt*128 + r0 + 8) * DD + h*HDIM + 2*tg;
        #pragma unroll
        for (int nt = 0; nt < 16; nt++) {
            *(__half2*)(op0 + nt*8) = __floats2half2_rn(oacc[nt][0]*inv0, oacc[nt][1]*inv0);
            *(__half2*)(op1 + nt*8) = __floats2half2_rn(oacc[nt][2]*inv1, oacc[nt][3]*inv1);
        }
    }
}

// ---------------- launch ----------------
extern "C" void kernel_launch(void* const* d_in, const int* in_sizes, int n_in,
                              void* d_out, int out_size)
{
    (void)in_sizes; (void)n_in; (void)out_size;
    const float* x   = (const float*)d_in[0];
    const float* ln1 = (const float*)d_in[2];
    const float* wq  = (const float*)d_in[3];
    const float* bq  = (const float*)d_in[4];
    const float* wk  = (const float*)d_in[5];
    const float* bk  = (const float*)d_in[6];
    const float* wv  = (const float*)d_in[7];
    const float* bv  = (const float*)d_in[8];
    const float* wo  = (const float*)d_in[9];
    const float* ln2 = (const float*)d_in[10];
    const float* wg  = (const float*)d_in[11];
    const float* wu  = (const float*)d_in[12];
    const float* wd  = (const float*)d_in[13];
    float* out = (float*)d_out;

    __half *h, *qkv, *attn, *g, *act;
    __half *rwqkv, *rwo, *rwgu, *rwd;
    float *h2, *bqkv;
    float2 *rope;
    cudaGetSymbolAddress((void**)&h,     g_h);
    cudaGetSymbolAddress((void**)&qkv,   g_qkv);
    cudaGetSymbolAddress((void**)&attn,  g_attn);
    cudaGetSymbolAddress((void**)&h2,    g_h2);
    cudaGetSymbolAddress((void**)&g,     g_g);
    cudaGetSymbolAddress((void**)&act,   g_act);
    cudaGetSymbolAddress((void**)&rwqkv, g_wqkv);
    cudaGetSymbolAddress((void**)&rwo,   g_wo);
    cudaGetSymbolAddress((void**)&rwgu,  g_wgu);
    cudaGetSymbolAddress((void**)&rwd,   g_wd);
    cudaGetSymbolAddress((void**)&bqkv,  g_bqkv);
    cudaGetSymbolAddress((void**)&rope,  g_rope);

    cudaFuncSetAttribute((const void*)hgemm_kernel<1,__half>, cudaFuncAttributeMaxDynamicSharedMemorySize, GEMM_SMEM);
    cudaFuncSetAttribute((const void*)hgemm_kernel<2,float>,  cudaFuncAttributeMaxDynamicSharedMemorySize, GEMM_SMEM);
    cudaFuncSetAttribute((const void*)hgemm_kernel<3,__half>, cudaFuncAttributeMaxDynamicSharedMemorySize, GEMM_SMEM);
    cudaFuncSetAttribute((const void*)flash_mma_kernel, cudaFuncAttributeMaxDynamicSharedMemorySize, FA_SMEM);

    // Streams + events: s2 = batch-1 chain, s3 = late-weight prepass
    static cudaStream_t s2 = nullptr, s3 = nullptr;
    static cudaEvent_t eFork = nullptr, eQkvw = nullptr,
                       eWo = nullptr, eGu = nullptr, eWd = nullptr, eJoin = nullptr;
    if (s2 == nullptr) {
        cudaStreamCreateWithFlags(&s2, cudaStreamNonBlocking);
        cudaStreamCreateWithFlags(&s3, cudaStreamNonBlocking);
        cudaEventCreateWithFlags(&eFork, cudaEventDisableTiming);
        cudaEventCreateWithFlags(&eQkvw, cudaEventDisableTiming);
        cudaEventCreateWithFlags(&eWo,   cudaEventDisableTiming);
        cudaEventCreateWithFlags(&eGu,   cudaEventDisableTiming);
        cudaEventCreateWithFlags(&eWd,   cudaEventDisableTiming);
        cudaEventCreateWithFlags(&eJoin, cudaEventDisableTiming);
    }

    // ---- fork s3 at entry: late-needed weights convert concurrently ----
    cudaEventRecord(eFork, 0);
    cudaStreamWaitEvent(s3, eFork, 0);
    f2h_kernel<<<(DD*DD/4)/256, 256, 0, s3>>>(wo, rwo);
    cudaEventRecord(eWo, s3);
    f2h_ilv_kernel<<<(II*DD/4)/256, 256, 0, s3>>>(wg, wu, rwgu);
    cudaEventRecord(eGu, s3);
    f2h_kernel<<<(DD*II/4)/256, 256, 0, s3>>>(wd, rwd);
    cudaEventRecord(eWd, s3);

    // ---- critical-path prepass (stream 0): only what QKV needs ----
    rope_table_kernel<<<(SS*64)/256, 256>>>(rope);
    f2h_kernel<<<(DD*DD/4)/256, 256>>>(wq, rwqkv);
    f2h_kernel<<<(256*DD/4)/256, 256>>>(wk, rwqkv + 2048*DD);
    f2h_kernel<<<(256*DD/4)/256, 256>>>(wv, rwqkv + 2304*DD);
    bias_concat_kernel<<<10, 256>>>(bq, bk, bv, bqkv);

    cudaEventRecord(eQkvw, 0);
    cudaStreamWaitEvent(s2, eQkvw, 0);

    // ---- per-batch chains: batch 0 on stream 0, batch 1 on s2 ----
    for (int b = 0; b < BB; b++) {
        cudaStream_t st = (b == 0) ? (cudaStream_t)0 : s2;
        const size_t m0 = (size_t)b * SS;

        // 1. h = rmsnorm(x, ln1)
        rmsnorm_kernel<<<SS, 256, 0, st>>>(x + m0*DD, ln1, h + m0*DD);

        // 2. fused qkv projection (+bias)
        hgemm_kernel<1,__half><<<dim3(QKVN/128, SS/128), 256, GEMM_SMEM, st>>>(
            h + m0*DD, rwqkv, bqkv, qkv + m0*QKVN, SS, QKVN, DD);

        // 3. K-rope (Q rope fused into attention)
        rope_k_kernel<<<(SS*KVH*64)/256, 256, 0, st>>>(qkv + m0*QKVN, rope);

        // 4. attention (paired q-tiles, per batch)
        flash_mma_kernel<<<dim3(NQT/2, HH), 256, FA_SMEM, st>>>(
            qkv + m0*QKVN, rope, attn + m0*DD);

        // 5. h2 = x + attn @ wo^T (fp32) — needs rwo
        cudaStreamWaitEvent(st, eWo, 0);
        hgemm_kernel<2,float><<<dim3(DD/128, SS/128), 256, GEMM_SMEM, st>>>(
            attn + m0*DD, rwo, x + m0*DD, h2 + m0*DD, SS, DD, DD);

        // 6. g = rmsnorm(h2, ln2)
        rmsnorm_kernel<<<SS, 256, 0, st>>>(h2 + m0*DD, ln2, g + m0*DD);

        // 7. fused MLP gate/up + silu — needs rwgu
        cudaStreamWaitEvent(st, eGu, 0);
        hgemm_kernel<3,__half><<<dim3(2*II/128, SS/128), 256, GEMM_SMEM, st>>>(
            g + m0*DD, rwgu, nullptr, act + m0*II, SS, II, DD);

        // 8. out = h2 + act @ wd^T (fp32) — needs rwd
        cudaStreamWaitEvent(st, eWd, 0);
        hgemm_kernel<2,float><<<dim3(DD/128, SS/128), 256, GEMM_SMEM, st>>>(
            act + m0*II, rwd, h2 + m0*DD, out + m0*DD, SS, DD, II);
    }

    // join: stream 0 waits for batch 1
    cudaEventRecord(eJoin, s2);
    cudaStreamWaitEvent(0, eJoin, 0);
}